// round 9
// baseline (speedup 1.0000x reference)
#include <cuda_runtime.h>
#include <cuda_fp16.h>
#include <cstdint>

#define HD 150
#define GDIM 1000
#define GRIDW 129
#define NCH1 9          // layer-1 fp8 chunks, K=128 bytes each

typedef unsigned long long ull;

// ---------------- helpers ----------------
__device__ __forceinline__ uint32_t smem_u32(const void* p){
    uint32_t a; asm("{ .reg .u64 t; cvta.to.shared.u64 t, %1; cvt.u32.u64 %0, t; }" : "=r"(a) : "l"(p));
    return a;
}
#define CVTB2(res,a,b) asm("cvt.rn.satfinite.bf16x2.f32 %0, %1, %2;" : "=r"(res) : "f"(b), "f"(a))
#define STS128(r0,r1,r2,r3,addr) asm volatile("st.shared.v4.b32 [%0], {%1,%2,%3,%4};" :: "r"(addr), "r"(r0), "r"(r1), "r"(r2), "r"(r3) : "memory")
#define SWZ(a) ((a) ^ (((a)>>3)&0x70))

__device__ __forceinline__ float2 unpack_bf2(uint32_t v){
    float2 r;
    r.x = __uint_as_float(v << 16);
    r.y = __uint_as_float(v & 0xffff0000u);
    return r;
}
__device__ __forceinline__ uint32_t mulh2(uint32_t a, uint32_t b){
    uint32_t r; asm("mul.rn.f16x2 %0,%1,%2;" : "=r"(r) : "r"(a), "r"(b)); return r;
}
// two f16x2 products -> 4 e4m3 bytes
__device__ __forceinline__ uint32_t pk_e4(uint32_t p0, uint32_t p1){
    unsigned short l, h;
    asm("cvt.rn.satfinite.e4m3x2.f16x2 %0, %1;" : "=h"(l) : "r"(p0));
    asm("cvt.rn.satfinite.e4m3x2.f16x2 %0, %1;" : "=h"(h) : "r"(p1));
    return (uint32_t)l | ((uint32_t)h << 16);
}
__device__ __forceinline__ uint8_t f2e4(float v){
    unsigned short t;
    asm("cvt.rn.satfinite.e4m3x2.f32 %0, %1, %2;" : "=h"(t) : "f"(0.f), "f"(v));
    return (uint8_t)t;
}

#define CPA16(dst,src) asm volatile("cp.async.cg.shared.global [%0], [%1], 16;" :: "r"((uint32_t)(dst)), "l"(src) : "memory")
#define CPC() asm volatile("cp.async.commit_group;" ::: "memory")
#define CPW0() asm volatile("cp.async.wait_group 0;" ::: "memory")
#define CPW1() asm volatile("cp.async.wait_group 1;" ::: "memory")
#define CPW2() asm volatile("cp.async.wait_group 2;" ::: "memory")

#define LDSM4(r0,r1,r2,r3,addr) \
    asm volatile("ldmatrix.sync.aligned.m8n8.x4.shared.b16 {%0,%1,%2,%3}, [%4];" \
        : "=r"(r0),"=r"(r1),"=r"(r2),"=r"(r3) : "r"(addr))
#define LDSM2(r0,r1,addr) \
    asm volatile("ldmatrix.sync.aligned.m8n8.x2.shared.b16 {%0,%1}, [%2];" \
        : "=r"(r0),"=r"(r1) : "r"(addr))

#define MMA_F16(d,a,b) \
    asm volatile("mma.sync.aligned.m16n8k16.row.col.f32.f16.f16.f32 " \
        "{%0,%1,%2,%3},{%4,%5,%6,%7},{%8,%9},{%0,%1,%2,%3};" \
        : "+f"((d)[0]),"+f"((d)[1]),"+f"((d)[2]),"+f"((d)[3]) \
        : "r"((a)[0]),"r"((a)[1]),"r"((a)[2]),"r"((a)[3]),"r"((b)[0]),"r"((b)[1]))
#define MMA_E4(d,a,b) \
    asm volatile("mma.sync.aligned.m16n8k32.row.col.f32.e4m3.e4m3.f32 " \
        "{%0,%1,%2,%3},{%4,%5,%6,%7},{%8,%9},{%0,%1,%2,%3};" \
        : "+f"((d)[0]),"+f"((d)[1]),"+f"((d)[2]),"+f"((d)[3]) \
        : "r"((a)[0]),"r"((a)[1]),"r"((a)[2]),"r"((a)[3]),"r"((b)[0]),"r"((b)[1]))

// ---------------- scratch ----------------
__device__ uint32_t g_gib[4096 * 512];          // gi as f16x2, K padded to 1024
__device__ uint32_t g_ABpack[2 * 16 * 5120];    // W1a^T, W1b^T f16 pre-swizzled (k_pre)
__device__ __align__(16) uint8_t g_Bpk8[NCH1 * 20480];  // 32*W1c^T / W1d^T e4m3 chunks
__device__ __align__(16) uint8_t g_W2pk8[2 * 20480];    // 16*W2^T e4m3 chunks
__device__ uint32_t g_A[4096 * 80];             // (gi@W1a + b1) bf16x2
__device__ uint32_t g_B[4096 * 80];             // (gi@W1b) bf16x2
__device__ float g_scores[132096];
__device__ int   g_starts[2048];

// ============================================================
// warp MMA consumer, N40. FP8=0: f16 k16 (kb = 32B = 16 elems)
//                         FP8=1: e4m3 k32 (kb = 32B = 32 elems)
// identical smem addressing in both cases.
// ============================================================
template<int MT, int FP8>
__device__ __forceinline__ void mma_chunk40(uint32_t Ab, uint32_t Bb, int nk,
                                            int mrow0, int nrow0, int lane,
                                            float (&acc)[MT][5][4])
{
    const int a_row = mrow0 + ((lane>>3)&1)*8 + (lane&7);
    const int a_cb  = (lane>>4)*16;
    const int b_row = nrow0 + ((lane>>4)&1)*8 + (lane&7);
    const int b_cb  = ((lane>>3)&1)*16;
    const int b2_row = nrow0 + 32 + (lane&7);
    const int b2_cb  = ((lane>>3)&1)*16;
    #pragma unroll
    for (int kq = 0; kq < nk; kq++) {
        const int kb = kq * 32;
        uint32_t a[MT][4];
        #pragma unroll
        for (int mt = 0; mt < MT; mt++) {
            uint32_t ad = Ab + SWZ((uint32_t)((a_row + mt*16)*128 + kb + a_cb));
            LDSM4(a[mt][0], a[mt][1], a[mt][2], a[mt][3], ad);
        }
        uint32_t b[5][2];
        #pragma unroll
        for (int g = 0; g < 2; g++) {
            uint32_t bd = Bb + SWZ((uint32_t)((b_row + g*16)*128 + kb + b_cb));
            uint32_t r0, r1, r2, r3;
            LDSM4(r0, r1, r2, r3, bd);
            b[2*g][0] = r0; b[2*g][1] = r1; b[2*g+1][0] = r2; b[2*g+1][1] = r3;
        }
        {
            uint32_t bd = Bb + SWZ((uint32_t)(b2_row*128 + kb + b2_cb));
            LDSM2(b[4][0], b[4][1], bd);
        }
        #pragma unroll
        for (int mt = 0; mt < MT; mt++)
            #pragma unroll
            for (int nt = 0; nt < 5; nt++) {
                if constexpr (FP8) { MMA_E4(acc[mt][nt], a[mt], b[nt]); }
                else               { MMA_F16(acc[mt][nt], a[mt], b[nt]); }
            }
    }
}

// ============================================================
// prep: gi->f16; ABpack f16; Bpk8/W2pk8 e4m3 (scaled); fill; starts
// ============================================================
__global__ void k_prep(const float* __restrict__ gi, const float* __restrict__ W1,
                       const float* __restrict__ W2,
                       const int* __restrict__ offs, const int* __restrict__ segs,
                       float* __restrict__ out, int NSPAN, int P, int out_total)
{
    long long idx = (long long)blockIdx.x * 256 + threadIdx.x;
    const long long NG  = (long long)NSPAN * 512;
    const long long AB  = NG + 2 * 16 * 5120;
    const long long BP  = AB + (long long)NCH1 * 20480;
    const long long B2E = BP + 2 * 20480;
    const long long FE  = B2E + out_total;
    const long long SE  = FE + P;
    if (idx < NG) {
        int n = (int)(idx >> 9), kw = (int)(idx & 511);
        int c0 = kw * 2;
        float a = (c0     < GDIM) ? gi[(size_t)n * GDIM + c0]     : 0.f;
        float b = (c0 + 1 < GDIM) ? gi[(size_t)n * GDIM + c0 + 1] : 0.f;
        __half2 hp = __floats2half2_rn(a, b);
        g_gib[idx] = *reinterpret_cast<uint32_t*>(&hp);
    } else if (idx < AB) {
        int t = (int)(idx - NG);
        int sel = t / (16 * 5120); int rem = t - sel * 16 * 5120;
        int c = rem / 5120, r = rem % 5120;
        int n = r >> 5, kk = (r & 31) * 2;
        int kg = c * 64 + kk;
        float v0 = 0.f, v1 = 0.f;
        if (n < HD) {
            if (kg     < GDIM) v0 = W1[(size_t)(sel * GDIM + kg)     * HD + n];
            if (kg + 1 < GDIM) v1 = W1[(size_t)(sel * GDIM + kg + 1) * HD + n];
        }
        __half2 hp = __floats2half2_rn(v0, v1);
        uint32_t off = (uint32_t)(n * 128 + kk * 2);
        g_ABpack[(sel * 16 + c) * 5120 + (SWZ(off) >> 2)] = *reinterpret_cast<uint32_t*>(&hp);
    } else if (idx < BP) {
        int t = (int)(idx - AB);
        int c = t / 20480, r = t - c * 20480;
        int n = r >> 7, kk = r & 127;
        float v = 0.f;
        if (n < HD) {
            if (c < 8) {
                int kg = c * 128 + kk;
                if (kg < GDIM) v = W1[(size_t)(2000 + kg) * HD + n] * 32.f;
            } else {
                if (kk < 60)   v = W1[(size_t)(3000 + kk) * HD + n];
            }
        }
        g_Bpk8[c * 20480 + SWZ((uint32_t)(n * 128 + kk))] = f2e4(v);
    } else if (idx < B2E) {
        int t = (int)(idx - BP);
        int c = t / 20480, r = t - c * 20480;
        int n = r >> 7, kk = r & 127;
        int h = c * 128 + kk;
        float v = (n < HD && h < HD) ? W2[(size_t)h * HD + n] * 16.f : 0.f;
        g_W2pk8[c * 20480 + SWZ((uint32_t)(n * 128 + kk))] = f2e4(v);
    } else if (idx < FE) {
        long long i = idx - B2E;
        out[i] = (i == 0) ? 1.0f : 1000.0f;
    } else if (idx < SE) {
        int p = (int)(idx - FE);
        if (offs[p] == 0) g_starts[segs[p]] = p;
    }
}

// ============================================================
// k_pre: g_A = (gi @ W1a) + b1, g_B = gi @ W1b  (f16 MMA, bf16x2 out)
// ============================================================
__global__ __launch_bounds__(512) void k_pre(const float* __restrict__ b1)
{
    extern __shared__ char dsm[];
    const int tid = threadIdx.x;
    const int lane = tid & 31;
    const int wid = tid >> 5;
    const int mw = wid & 3, nw = wid >> 2;
    const int n0 = blockIdx.x * 64;
    const int sel = blockIdx.y;

    uint32_t rbase = (smem_u32(dsm) + 1023u) & ~1023u;
    const char* Bsrc = (const char*)(g_ABpack + sel * 16 * 5120);

    float acc[1][5][4];
    #pragma unroll
    for (int j = 0; j < 5; j++)
        #pragma unroll
        for (int k = 0; k < 4; k++) acc[0][j][k] = 0.f;

    auto issue = [&](int c) {
        int s = c & 3;
        uint32_t Ab = rbase + (uint32_t)(s * 8192);
        uint32_t Bb = rbase + 32768u + (uint32_t)(s * 20480);
        {
            int row = tid >> 3, seg = tid & 7;
            const char* src = (const char*)g_gib + ((size_t)(n0 + row) * 2048 + c * 128 + seg * 16);
            CPA16(Ab + SWZ((uint32_t)(row * 128 + seg * 16)), src);
        }
        #pragma unroll
        for (int t = 0; t < 3; t++) {
            int j = tid + t * 512;
            if (j < 1280) CPA16(Bb + (uint32_t)(j * 16), Bsrc + (size_t)c * 20480 + j * 16);
        }
        CPC();
    };

    issue(0); issue(1); issue(2);
    for (int c = 0; c < 16; c++) {
        if (c <= 13) CPW2(); else if (c == 14) CPW1(); else CPW0();
        __syncthreads();
        if (c + 3 < 16) issue(c + 3);
        int s = c & 3;
        mma_chunk40<1,0>(rbase + (uint32_t)(s * 8192),
                         rbase + 32768u + (uint32_t)(s * 20480),
                         4, mw * 16, nw * 40, lane, acc);
    }

    uint32_t* dst = sel ? g_B : g_A;
    #pragma unroll
    for (int half = 0; half < 2; half++) {
        int row = n0 + mw * 16 + (lane >> 2) + half * 8;
        #pragma unroll
        for (int nt = 0; nt < 5; nt++) {
            int cc = nw * 40 + nt * 8 + (lane & 3) * 2;
            float x = acc[0][nt][half * 2];
            float y = acc[0][nt][half * 2 + 1];
            if (!sel) { x += b1[cc]; y += b1[cc + 1]; }
            uint32_t w; CVTB2(w, x, y);
            dst[(size_t)row * 80 + (cc >> 1)] = w;
        }
    }
}

// ============================================================
// fused pair kernel (FP8): layer1 e4m3 MMA + relu + layer2 e4m3 + score
// 512 threads, 4x4 warps M32xN40, 9 chunks of K=128, 4-deep B ring
// ============================================================
__global__ __launch_bounds__(512) void k_fused(
    const float* __restrict__ b2,
    const float* __restrict__ W3, const float* __restrict__ b3,
    const float* __restrict__ ms,
    const float* __restrict__ de, const float* __restrict__ ge, const float* __restrict__ se,
    const int* __restrict__ mi, const int* __restrict__ ai,
    const int* __restrict__ di, const int* __restrict__ gx, const int* __restrict__ si,
    int P)
{
    extern __shared__ char dsm[];
    __shared__ int smi[128], sai[128], sdi[128], sgi[128], ssi[128];
    __shared__ __align__(16) float s_b2[160], s_w3[160];
    __shared__ float sred[128][4];

    const int tid = threadIdx.x;
    const int lane = tid & 31;
    const int wid = tid >> 5;
    const int mw = wid & 3, nw = wid >> 2;
    const int p0 = blockIdx.x * 128;

    uint32_t rbase = (smem_u32(dsm) + 1023u) & ~1023u;
    // layer1: A bufs 2x16KB [0,32768); B ring 4x20KB [32768,114688)
    // layer2: H 2x16KB at rbase; W2 2x20KB at rbase+32768
    const uint32_t W2b = rbase + 32768u;

    if (tid < 128) {
        int p = p0 + tid; if (p >= P) p = P - 1;
        smi[tid] = mi[p]; sai[tid] = ai[p];
        sdi[tid] = di[p]; sgi[tid] = gx[p]; ssi[tid] = si[p];
    }
    if (tid >= 256 && tid < 416) {
        int h = tid - 256;
        s_b2[h] = (h < HD) ? b2[h] : 0.f;
        s_w3[h] = (h < HD) ? W3[h] : 0.f;
    }
    __syncthreads();

    float acc[2][5][4];
    #pragma unroll
    for (int i = 0; i < 2; i++)
        #pragma unroll
        for (int j = 0; j < 5; j++)
            #pragma unroll
            for (int k = 0; k < 4; k++) acc[i][j][k] = 0.f;

    const int m = tid >> 2, q = tid & 3;   // 4 threads per row, 32 bytes each

    uint4 iA[4];    // i-side prefetch (16 regs)
    auto loadI = [&](int c) {
        const uint4* Ip = ((const uint4*)g_gib) + ((size_t)smi[m] * 128 + c * 16 + q * 4);
        iA[0] = Ip[0]; iA[1] = Ip[1]; iA[2] = Ip[2]; iA[3] = Ip[3];
    };
    auto storeA = [&](int c) {
        const uint4* Jp = ((const uint4*)g_gib) + ((size_t)sai[m] * 128 + c * 16 + q * 4);
        uint32_t asb = rbase + (uint32_t)((c & 1) * 16384) + (uint32_t)(m * 128 + q * 32);
        #pragma unroll
        for (int t = 0; t < 2; t++) {
            uint4 i0 = iA[2*t], i1 = iA[2*t+1];
            uint4 j0 = Jp[2*t], j1 = Jp[2*t+1];
            uint32_t w0 = pk_e4(mulh2(i0.x, j0.x), mulh2(i0.y, j0.y));
            uint32_t w1 = pk_e4(mulh2(i0.z, j0.z), mulh2(i0.w, j0.w));
            uint32_t w2 = pk_e4(mulh2(i1.x, j1.x), mulh2(i1.y, j1.y));
            uint32_t w3 = pk_e4(mulh2(i1.z, j1.z), mulh2(i1.w, j1.w));
            STS128(w0, w1, w2, w3, SWZ(asb + t * 16));
        }
    };
    auto producePhi = [&]() {   // chunk 8 -> buf 0; phi scaled x32, bytes>=60 zero
        uint32_t asb = rbase + (uint32_t)(m * 128 + q * 32);
        #pragma unroll
        for (int t4 = 0; t4 < 2; t4++) {
            uint32_t w[4];
            #pragma unroll
            for (int wi = 0; wi < 4; wi++) {
                float f[4];
                #pragma unroll
                for (int e = 0; e < 4; e++) {
                    int kk = q * 32 + t4 * 16 + wi * 4 + e;
                    float v = 0.f;
                    if (kk < 20)      v = de[sdi[m] * 20 + kk];
                    else if (kk < 40) v = ge[sgi[m] * 20 + kk - 20];
                    else if (kk < 60) v = se[ssi[m] * 20 + kk - 40];
                    f[e] = v * 32.f;
                }
                unsigned short l, h;
                asm("cvt.rn.satfinite.e4m3x2.f32 %0, %1, %2;" : "=h"(l) : "f"(f[1]), "f"(f[0]));
                asm("cvt.rn.satfinite.e4m3x2.f32 %0, %1, %2;" : "=h"(h) : "f"(f[3]), "f"(f[2]));
                w[wi] = (uint32_t)l | ((uint32_t)h << 16);
            }
            STS128(w[0], w[1], w[2], w[3], SWZ(asb + t4 * 16));
        }
    };
    auto issueB = [&](int c) {
        uint32_t Bb = rbase + 32768u + (uint32_t)((c & 3) * 20480);
        const char* src = (const char*)g_Bpk8 + (size_t)c * 20480;
        #pragma unroll
        for (int t = 0; t < 3; t++) {
            int i = tid + t * 512;
            if (i < 1280) CPA16(Bb + (uint32_t)(i * 16), src + (size_t)i * 16);
        }
        CPC();
    };

    // ---- layer 1 pipeline: 9 chunks, B 3 ahead, 1 barrier/chunk ----
    issueB(0); issueB(1); issueB(2);
    loadI(0);
    storeA(0);
    for (int c = 0; c < NCH1; c++) {
        if (c + 1 < 8) loadI(c + 1);
        if (c <= 6) CPW2(); else if (c == 7) CPW1(); else CPW0();
        __syncthreads();
        if (c + 3 < NCH1) issueB(c + 3);
        mma_chunk40<2,1>(rbase + (uint32_t)((c & 1) * 16384),
                         rbase + 32768u + (uint32_t)((c & 3) * 20480),
                         4, mw * 32, nw * 40, lane, acc);
        if (c + 1 < NCH1) {
            if (c + 1 < 8) storeA(c + 1); else producePhi();
        }
    }
    __syncthreads();   // all LDSM reads done before H/W2 overwrite

    // ---- W2^T cp.async (2 chunks = 40KB) ----
    {
        const uint4* src = (const uint4*)g_W2pk8;
        #pragma unroll
        for (int t = 0; t < 5; t++) {
            int i = tid + t * 512;
            if (i < 2560) CPA16(W2b + (uint32_t)(i * 16), src + i);
        }
        CPC();
    }

    // ---- epilogue 1: acc/32 + base, relu -> e4m3 H tile ----
    #pragma unroll
    for (int mt = 0; mt < 2; mt++)
        #pragma unroll
        for (int half = 0; half < 2; half++) {
            int r = mw * 32 + mt * 16 + (lane >> 2) + half * 8;
            const uint32_t* Ar = g_A + (size_t)smi[r] * 80;
            const uint32_t* Br = g_B + (size_t)sai[r] * 80;
            #pragma unroll
            for (int nt = 0; nt < 5; nt++) {
                int cc = nw * 40 + nt * 8 + (lane & 3) * 2;
                float2 av = unpack_bf2(Ar[cc >> 1]);
                float2 bv = unpack_bf2(Br[cc >> 1]);
                float x = fmaxf(acc[mt][nt][half * 2]     * 0.03125f + av.x + bv.x, 0.f);
                float y = fmaxf(acc[mt][nt][half * 2 + 1] * 0.03125f + av.y + bv.y, 0.f);
                unsigned short hw;
                asm("cvt.rn.satfinite.e4m3x2.f32 %0, %1, %2;" : "=h"(hw) : "f"(y), "f"(x));
                uint32_t addr = rbase + (uint32_t)((cc >> 7) * 16384) +
                                SWZ((uint32_t)(r * 128 + (cc & 127)));
                asm volatile("st.shared.u16 [%0], %1;" :: "r"(addr), "h"(hw) : "memory");
            }
        }
    // zero H chunk1 bytes 32..127 (avoid stale-NaN * 0 in fp8 MMA)
    for (int t = tid; t < 768; t += 512) {
        int r = t / 6, j = t - r * 6;
        STS128(0u, 0u, 0u, 0u, rbase + 16384u + SWZ((uint32_t)(r * 128 + 32 + j * 16)));
    }
    CPW0();
    __syncthreads();

    // ---- layer 2: K=160 fp8 (chunk0 nk=4, chunk1 nk=1) ----
    #pragma unroll
    for (int i = 0; i < 2; i++)
        #pragma unroll
        for (int j = 0; j < 5; j++)
            #pragma unroll
            for (int k = 0; k < 4; k++) acc[i][j][k] = 0.f;
    mma_chunk40<2,1>(rbase,           W2b,           4, mw * 32, nw * 40, lane, acc);
    mma_chunk40<2,1>(rbase + 16384u,  W2b + 20480u,  1, mw * 32, nw * 40, lane, acc);

    // ---- epilogue 2: relu(acc/16 + b2) . W3 -> scores ----
    #pragma unroll
    for (int mt = 0; mt < 2; mt++)
        #pragma unroll
        for (int half = 0; half < 2; half++) {
            float part = 0.f;
            #pragma unroll
            for (int nt = 0; nt < 5; nt++) {
                int cc = nw * 40 + nt * 8 + (lane & 3) * 2;
                float h0 = fmaxf(acc[mt][nt][half * 2]     * 0.0625f + s_b2[cc],     0.f);
                float h1 = fmaxf(acc[mt][nt][half * 2 + 1] * 0.0625f + s_b2[cc + 1], 0.f);
                part += h0 * s_w3[cc] + h1 * s_w3[cc + 1];
            }
            part += __shfl_xor_sync(0xffffffffu, part, 1);
            part += __shfl_xor_sync(0xffffffffu, part, 2);
            if ((lane & 3) == 0) {
                int r = mw * 32 + mt * 16 + (lane >> 2) + half * 8;
                sred[r][nw] = part;
            }
        }
    __syncthreads();
    if (tid < 128) {
        int p = p0 + tid;
        if (p < P) {
            float s = sred[tid][0] + sred[tid][1] + sred[tid][2] + sred[tid][3]
                    + b3[0] + ms[smi[tid]] + ms[sai[tid]];
            g_scores[p] = s;
        }
    }
}

// ============================================================
__global__ __launch_bounds__(128) void k_softmax(const int* __restrict__ lengths,
                                                 float* __restrict__ out)
{
    int g = blockIdx.x;
    int tid = threadIdx.x;
    int len = lengths[g];
    int st = g_starts[g];
    __shared__ float sm[4], ss[4];

    float v = (tid < len) ? g_scores[st + tid] : -3.4e38f;
    float mx = v;
    #pragma unroll
    for (int o = 16; o > 0; o >>= 1) mx = fmaxf(mx, __shfl_xor_sync(0xffffffffu, mx, o));
    if ((tid & 31) == 0) sm[tid >> 5] = mx;
    __syncthreads();
    mx = fmaxf(fmaxf(sm[0], sm[1]), fmaxf(sm[2], sm[3]));
    mx = fmaxf(mx, 0.f);

    float e = (tid < len) ? expf(v - mx) : 0.f;
    float s = e;
    #pragma unroll
    for (int o = 16; o > 0; o >>= 1) s += __shfl_xor_sync(0xffffffffu, s, o);
    if ((tid & 31) == 0) ss[tid >> 5] = s;
    __syncthreads();

    float epse = expf(-mx);
    float denom = ss[0] + ss[1] + ss[2] + ss[3] + epse;
    float* row = out + (size_t)(g + 1) * GRIDW;
    if (tid < len) row[tid] = e / denom;
    if (tid == 0)  row[len] = epse / denom;
}

// ============================================================
extern "C" void kernel_launch(void* const* d_in, const int* in_sizes, int n_in,
                              void* d_out, int out_size)
{
    const float* gi   = (const float*)d_in[0];
    const float* ms   = (const float*)d_in[1];
    const float* de   = (const float*)d_in[2];
    const float* ge   = (const float*)d_in[3];
    const float* se   = (const float*)d_in[4];
    const float* W1   = (const float*)d_in[5];
    const float* b1   = (const float*)d_in[6];
    const float* W2   = (const float*)d_in[7];
    const float* b2   = (const float*)d_in[8];
    const float* W3   = (const float*)d_in[9];
    const float* b3   = (const float*)d_in[10];
    const int*   mi   = (const int*)d_in[11];
    const int*   ai   = (const int*)d_in[12];
    const int*   di   = (const int*)d_in[13];
    const int*   gidx = (const int*)d_in[14];
    const int*   si   = (const int*)d_in[15];
    const int*   lens = (const int*)d_in[16];
    const int*   segs = (const int*)d_in[17];
    const int*   offs = (const int*)d_in[18];
    float* out = (float*)d_out;

    const int P = in_sizes[11];
    const int M = in_sizes[16];
    const int NSPAN = in_sizes[0] / GDIM;   // 4096

    const int DS = 114688 + 1024;
    static int configured = 0;
    if (!configured) {
        cudaFuncSetAttribute(k_pre,   cudaFuncAttributeMaxDynamicSharedMemorySize, DS);
        cudaFuncSetAttribute(k_fused, cudaFuncAttributeMaxDynamicSharedMemorySize, DS);
        configured = 1;
    }

    long long prep_total = (long long)NSPAN * 512 + 2 * 16 * 5120
                         + (long long)NCH1 * 20480 + 2 * 20480
                         + out_size + P;
    k_prep<<<(int)((prep_total + 255) / 256), 256>>>(gi, W1, W2, offs, segs, out,
                                                     NSPAN, P, out_size);

    k_pre<<<dim3(NSPAN / 64, 2), 512, DS>>>(b1);

    int NT = (P + 127) / 128;
    k_fused<<<NT, 512, DS>>>(b2, W3, b3, ms, de, ge, se,
                             mi, ai, di, gidx, si, P);

    k_softmax<<<M, 128>>>(lens, out);
}

// round 10
// speedup vs baseline: 1.3603x; 1.3603x over previous
#include <cuda_runtime.h>
#include <cuda_bf16.h>
#include <cstdint>

#define HD 150
#define HP 160
#define GDIM 1000
#define GRIDW 129
#define NCHUNK 16

typedef unsigned long long ull;

// ---------------- helpers ----------------
__device__ __forceinline__ uint32_t smem_u32(const void* p){
    uint32_t a; asm("{ .reg .u64 t; cvta.to.shared.u64 t, %1; cvt.u32.u64 %0, t; }" : "=r"(a) : "l"(p));
    return a;
}
__device__ __forceinline__ uint32_t mul2(uint32_t a, uint32_t b){
    uint32_t r; asm("mul.bf16x2 %0,%1,%2;" : "=r"(r) : "r"(a), "r"(b)); return r;
}
#define CVTB2(res,a,b) asm("cvt.rn.satfinite.bf16x2.f32 %0, %1, %2;" : "=r"(res) : "f"(b), "f"(a))
#define STS128(r0,r1,r2,r3,addr) asm volatile("st.shared.v4.b32 [%0], {%1,%2,%3,%4};" :: "r"(addr), "r"(r0), "r"(r1), "r"(r2), "r"(r3) : "memory")
#define STS32(addr,v) asm volatile("st.shared.b32 [%0], %1;" :: "r"(addr), "r"(v) : "memory")
#define SWZ(a) ((a) ^ (((a)>>3)&0x70))

__device__ __forceinline__ float2 unpack_bf2(uint32_t v){
    float2 r;
    r.x = __uint_as_float(v << 16);
    r.y = __uint_as_float(v & 0xffff0000u);
    return r;
}

#define CPA16(dst,src) asm volatile("cp.async.cg.shared.global [%0], [%1], 16;" :: "r"((uint32_t)(dst)), "l"(src) : "memory")
#define CPC() asm volatile("cp.async.commit_group;" ::: "memory")
#define CPW0() asm volatile("cp.async.wait_group 0;" ::: "memory")
#define CPW1() asm volatile("cp.async.wait_group 1;" ::: "memory")
#define CPW2() asm volatile("cp.async.wait_group 2;" ::: "memory")

#define LDSM4(r0,r1,r2,r3,addr) \
    asm volatile("ldmatrix.sync.aligned.m8n8.x4.shared.b16 {%0,%1,%2,%3}, [%4];" \
        : "=r"(r0),"=r"(r1),"=r"(r2),"=r"(r3) : "r"(addr))
#define LDSM2(r0,r1,addr) \
    asm volatile("ldmatrix.sync.aligned.m8n8.x2.shared.b16 {%0,%1}, [%2];" \
        : "=r"(r0),"=r"(r1) : "r"(addr))

#define MMA(d,a,b) \
    asm volatile("mma.sync.aligned.m16n8k16.row.col.f32.bf16.bf16.f32 " \
        "{%0,%1,%2,%3},{%4,%5,%6,%7},{%8,%9},{%0,%1,%2,%3};" \
        : "+f"((d)[0]),"+f"((d)[1]),"+f"((d)[2]),"+f"((d)[3]) \
        : "r"((a)[0]),"r"((a)[1]),"r"((a)[2]),"r"((a)[3]),"r"((b)[0]),"r"((b)[1]))

// ---------------- scratch ----------------
__device__ uint32_t g_gib[4096 * 512];          // gi as bf16x2, K padded to 1024
__device__ uint32_t g_ABpack[2 * 16 * 5120];    // W1a^T, W1b^T pre-swizzled chunks
__device__ uint32_t g_Bpack[NCHUNK * 5120];     // W1c^T chunks (product block only)
__device__ uint32_t g_B2pack[3 * 5120];         // W2^T chunks
__device__ uint32_t g_A[4096 * 80];             // (gi@W1a + b1) bf16x2
__device__ uint32_t g_B[4096 * 80];             // (gi@W1b) bf16x2
__device__ uint32_t g_T[20 * 80];               // phi tables bf16x2: dist 0..8, genre 9..16, spk 17..19
__device__ float g_scores[132096];
__device__ int   g_starts[2048];

// ============================================================
// warp MMA consumer, N40: per k16 -> 2x LDSM4 + 1x LDSM2 for B
// ============================================================
template<int MT>
__device__ __forceinline__ void mma_chunk40(uint32_t Ab, uint32_t Bb, int nk16,
                                            int mrow0, int nrow0, int lane,
                                            float (&acc)[MT][5][4])
{
    const int a_row = mrow0 + ((lane>>3)&1)*8 + (lane&7);
    const int a_cb  = (lane>>4)*16;
    const int b_row = nrow0 + ((lane>>4)&1)*8 + (lane&7);
    const int b_cb  = ((lane>>3)&1)*16;
    const int b2_row = nrow0 + 32 + (lane&7);
    const int b2_cb  = ((lane>>3)&1)*16;
    #pragma unroll
    for (int k16 = 0; k16 < nk16; k16++) {
        const int kb = k16 * 32;
        uint32_t a[MT][4];
        #pragma unroll
        for (int mt = 0; mt < MT; mt++) {
            uint32_t ad = Ab + SWZ((uint32_t)((a_row + mt*16)*128 + kb + a_cb));
            LDSM4(a[mt][0], a[mt][1], a[mt][2], a[mt][3], ad);
        }
        uint32_t b[5][2];
        #pragma unroll
        for (int g = 0; g < 2; g++) {
            uint32_t bd = Bb + SWZ((uint32_t)((b_row + g*16)*128 + kb + b_cb));
            uint32_t r0, r1, r2, r3;
            LDSM4(r0, r1, r2, r3, bd);
            b[2*g][0] = r0; b[2*g][1] = r1; b[2*g+1][0] = r2; b[2*g+1][1] = r3;
        }
        {
            uint32_t bd = Bb + SWZ((uint32_t)(b2_row*128 + kb + b2_cb));
            LDSM2(b[4][0], b[4][1], bd);
        }
        #pragma unroll
        for (int mt = 0; mt < MT; mt++)
            #pragma unroll
            for (int nt = 0; nt < 5; nt++)
                MMA(acc[mt][nt], a[mt], b[nt]);
    }
}

// ============================================================
// prep (fused with fill + starts + phi tables)
// ============================================================
__global__ void k_prep(const float* __restrict__ gi, const float* __restrict__ W1,
                       const float* __restrict__ W2,
                       const float* __restrict__ de, const float* __restrict__ ge,
                       const float* __restrict__ se,
                       const int* __restrict__ offs, const int* __restrict__ segs,
                       float* __restrict__ out, int NSPAN, int P, int out_total)
{
    long long idx = (long long)blockIdx.x * 256 + threadIdx.x;
    const long long NG  = (long long)NSPAN * 512;
    const long long AB  = NG + 2 * 16 * 5120;
    const long long BP  = AB + NCHUNK * 5120;
    const long long B2E = BP + 3 * 5120;
    const long long TE  = B2E + 20 * 80;
    const long long FE  = TE + out_total;
    const long long SE  = FE + P;
    if (idx < NG) {
        int n = (int)(idx >> 9), kw = (int)(idx & 511);
        int c0 = kw * 2;
        float a = (c0     < GDIM) ? gi[(size_t)n * GDIM + c0]     : 0.f;
        float b = (c0 + 1 < GDIM) ? gi[(size_t)n * GDIM + c0 + 1] : 0.f;
        uint32_t w; CVTB2(w, a, b);
        g_gib[idx] = w;
    } else if (idx < AB) {
        int t = (int)(idx - NG);
        int sel = t / (16 * 5120); int rem = t - sel * 16 * 5120;
        int c = rem / 5120, r = rem % 5120;
        int n = r >> 5, kk = (r & 31) * 2;
        int kg = c * 64 + kk;
        float v0 = 0.f, v1 = 0.f;
        if (n < HD) {
            if (kg     < GDIM) v0 = W1[(size_t)(sel * GDIM + kg)     * HD + n];
            if (kg + 1 < GDIM) v1 = W1[(size_t)(sel * GDIM + kg + 1) * HD + n];
        }
        uint32_t w; CVTB2(w, v0, v1);
        uint32_t off = (uint32_t)(n * 128 + kk * 2);
        g_ABpack[(sel * 16 + c) * 5120 + (SWZ(off) >> 2)] = w;
    } else if (idx < BP) {
        int t = (int)(idx - AB);
        int c = t / 5120, r = t % 5120;
        int n = r >> 5, kk = (r & 31) * 2;
        int kg = c * 64 + kk;
        float v0 = 0.f, v1 = 0.f;
        if (n < HD) {
            if (kg     < GDIM) v0 = W1[(size_t)(2000 + kg) * HD + n];
            if (kg + 1 < GDIM) v1 = W1[(size_t)(2001 + kg) * HD + n];
        }
        uint32_t w; CVTB2(w, v0, v1);
        uint32_t off = (uint32_t)(n * 128 + kk * 2);
        g_Bpack[c * 5120 + (SWZ(off) >> 2)] = w;
    } else if (idx < B2E) {
        int t = (int)(idx - BP);
        int c = t / 5120, r = t % 5120;
        int n = r >> 5, kk = (r & 31) * 2;
        int kg = c * 64 + kk;
        float v0 = 0.f, v1 = 0.f;
        if (n < HD) {
            if (kg     < HD) v0 = W2[(size_t)kg       * HD + n];
            if (kg + 1 < HD) v1 = W2[(size_t)(kg + 1) * HD + n];
        }
        uint32_t w; CVTB2(w, v0, v1);
        uint32_t off = (uint32_t)(n * 128 + kk * 2);
        g_B2pack[c * 5120 + (SWZ(off) >> 2)] = w;
    } else if (idx < TE) {
        // phi tables: row r (0..19), cols cc, cc+1 ; T = emb_row @ W1d_block
        int t = (int)(idx - B2E);
        int r = t / 80, cc = (t % 80) * 2;
        const float* emb; int wbase, nk = 20;
        if (r < 9)       { emb = de + r * 20;        wbase = 3000; }
        else if (r < 17) { emb = ge + (r - 9) * 20;  wbase = 3020; }
        else             { emb = se + (r - 17) * 20; wbase = 3040; }
        float v0 = 0.f, v1 = 0.f;
        if (cc < HD) {
            for (int k = 0; k < nk; k++) {
                float e = emb[k];
                v0 += e * W1[(size_t)(wbase + k) * HD + cc];
                if (cc + 1 < HD) v1 += e * W1[(size_t)(wbase + k) * HD + cc + 1];
            }
        }
        uint32_t w; CVTB2(w, v0, v1);
        g_T[r * 80 + (cc >> 1)] = w;
    } else if (idx < FE) {
        long long i = idx - TE;
        out[i] = (i == 0) ? 1.0f : 1000.0f;
    } else if (idx < SE) {
        int p = (int)(idx - FE);
        if (offs[p] == 0) g_starts[segs[p]] = p;
    }
}

// ============================================================
// k_pre: g_A = (gi @ W1a) + b1, g_B = gi @ W1b   (bf16x2 output)
// ============================================================
__global__ __launch_bounds__(512) void k_pre(const float* __restrict__ b1)
{
    extern __shared__ char dsm[];
    const int tid = threadIdx.x;
    const int lane = tid & 31;
    const int wid = tid >> 5;
    const int mw = wid & 3, nw = wid >> 2;
    const int n0 = blockIdx.x * 64;
    const int sel = blockIdx.y;

    uint32_t rbase = (smem_u32(dsm) + 1023u) & ~1023u;
    const char* Bsrc = (const char*)(g_ABpack + sel * 16 * 5120);

    float acc[1][5][4];
    #pragma unroll
    for (int j = 0; j < 5; j++)
        #pragma unroll
        for (int k = 0; k < 4; k++) acc[0][j][k] = 0.f;

    auto issue = [&](int c) {
        int s = c & 3;
        uint32_t Ab = rbase + (uint32_t)(s * 8192);
        uint32_t Bb = rbase + 32768u + (uint32_t)(s * 20480);
        {
            int row = tid >> 3, seg = tid & 7;
            const char* src = (const char*)g_gib + ((size_t)(n0 + row) * 2048 + c * 128 + seg * 16);
            CPA16(Ab + SWZ((uint32_t)(row * 128 + seg * 16)), src);
        }
        #pragma unroll
        for (int t = 0; t < 3; t++) {
            int j = tid + t * 512;
            if (j < 1280) CPA16(Bb + (uint32_t)(j * 16), Bsrc + (size_t)c * 20480 + j * 16);
        }
        CPC();
    };

    issue(0); issue(1); issue(2);
    for (int c = 0; c < 16; c++) {
        if (c <= 13) CPW2(); else if (c == 14) CPW1(); else CPW0();
        __syncthreads();
        if (c + 3 < 16) issue(c + 3);
        int s = c & 3;
        mma_chunk40<1>(rbase + (uint32_t)(s * 8192),
                       rbase + 32768u + (uint32_t)(s * 20480),
                       4, mw * 16, nw * 40, lane, acc);
    }

    uint32_t* dst = sel ? g_B : g_A;
    #pragma unroll
    for (int half = 0; half < 2; half++) {
        int row = n0 + mw * 16 + (lane >> 2) + half * 8;
        #pragma unroll
        for (int nt = 0; nt < 5; nt++) {
            int cc = nw * 40 + nt * 8 + (lane & 3) * 2;
            float x = acc[0][nt][half * 2];
            float y = acc[0][nt][half * 2 + 1];
            if (!sel) { x += b1[cc]; y += b1[cc + 1]; }
            uint32_t w; CVTB2(w, x, y);
            dst[(size_t)row * 80 + (cc >> 1)] = w;
        }
    }
}

// ============================================================
// fused pair kernel: layer1 HMMA (product only) + relu(+tables) + layer2 + score
// 4-deep B ring, one barrier per chunk, 512 threads, 4x4 warps M32xN40
// ============================================================
__global__ __launch_bounds__(512) void k_fused(
    const float* __restrict__ b2,
    const float* __restrict__ W3, const float* __restrict__ b3,
    const float* __restrict__ ms,
    const int* __restrict__ mi, const int* __restrict__ ai,
    const int* __restrict__ di, const int* __restrict__ gx, const int* __restrict__ si,
    int P)
{
    extern __shared__ char dsm[];
    __shared__ int smi[128], sai[128], sdi[128], sgi[128], ssi[128];
    __shared__ __align__(16) float s_b2[HP], s_w3[HP];
    __shared__ float sred[128][4];

    const int tid = threadIdx.x;
    const int lane = tid & 31;
    const int wid = tid >> 5;
    const int mw = wid & 3, nw = wid >> 2;
    const int p0 = blockIdx.x * 128;

    uint32_t rbase = (smem_u32(dsm) + 1023u) & ~1023u;
    const uint32_t Hb  = rbase;
    const uint32_t W2b = rbase + 53248u;

    if (tid < 128) {
        int p = p0 + tid; if (p >= P) p = P - 1;
        smi[tid] = mi[p]; sai[tid] = ai[p];
        sdi[tid] = di[p]; sgi[tid] = gx[p]; ssi[tid] = si[p];
    }
    if (tid >= 256 && tid < 256 + HP) {
        int h = tid - 256;
        s_b2[h] = (h < HD) ? b2[h] : 0.f;
        s_w3[h] = (h < HD) ? W3[h] : 0.f;
    }
    __syncthreads();

    float acc[2][5][4];
    #pragma unroll
    for (int i = 0; i < 2; i++)
        #pragma unroll
        for (int j = 0; j < 5; j++)
            #pragma unroll
            for (int k = 0; k < 4; k++) acc[i][j][k] = 0.f;

    const int m = tid >> 2, q = tid & 3;

    uint4 iA[2], jA[2];
    auto loadA = [&](int c) {
        const uint4* Ip = ((const uint4*)g_gib) + ((size_t)smi[m] * 128 + c * 8 + q * 2);
        const uint4* Jp = ((const uint4*)g_gib) + ((size_t)sai[m] * 128 + c * 8 + q * 2);
        iA[0] = Ip[0]; iA[1] = Ip[1];
        jA[0] = Jp[0]; jA[1] = Jp[1];
    };
    auto storeA = [&](int c) {
        uint32_t asb = rbase + (uint32_t)((c & 1) * 16384) + (uint32_t)(m * 128 + q * 32);
        #pragma unroll
        for (int t = 0; t < 2; t++) {
            uint4 r;
            r.x = mul2(iA[t].x, jA[t].x); r.y = mul2(iA[t].y, jA[t].y);
            r.z = mul2(iA[t].z, jA[t].z); r.w = mul2(iA[t].w, jA[t].w);
            STS128(r.x, r.y, r.z, r.w, SWZ(asb + t * 16));
        }
    };
    auto issueB = [&](int c) {
        uint32_t Bb = rbase + 32768u + (uint32_t)((c & 3) * 20480);
        const char* src = (const char*)(g_Bpack + c * 5120);
        #pragma unroll
        for (int t = 0; t < 3; t++) {
            int i = tid + t * 512;
            if (i < 1280) CPA16(Bb + (uint32_t)(i * 16), src + (size_t)i * 16);
        }
        CPC();
    };

    // ---- layer 1 pipeline: B 3 chunks ahead, 1 barrier/chunk ----
    issueB(0); issueB(1); issueB(2);
    loadA(0);
    storeA(0);
    for (int c = 0; c < NCHUNK; c++) {
        if (c + 1 < NCHUNK) loadA(c + 1);
        if (c < NCHUNK - 2) CPW2(); else if (c == NCHUNK - 2) CPW1(); else CPW0();
        __syncthreads();
        if (c + 3 < NCHUNK) issueB(c + 3);
        int s = c & 3;
        mma_chunk40<2>(rbase + (uint32_t)((c & 1) * 16384),
                       rbase + 32768u + (uint32_t)(s * 20480),
                       4, mw * 32, nw * 40, lane, acc);
        if (c + 1 < NCHUNK) storeA(c + 1);
    }
    __syncthreads();   // all MMA reads done before H/W2 overwrite A/B regions

    // ---- W2^T cp.async ----
    {
        const char* src = (const char*)g_B2pack;
        #pragma unroll
        for (int t = 0; t < 8; t++) {
            int i = tid + t * 512;
            if (i < 3840) CPA16(W2b + (uint32_t)(i * 16), src + (size_t)i * 16);
        }
        CPC();
    }

    // ---- epilogue 1: +(A[mi]+b1)+(B[ai])+phi tables, relu -> bf16 H tile ----
    #pragma unroll
    for (int mt = 0; mt < 2; mt++)
        #pragma unroll
        for (int half = 0; half < 2; half++) {
            int r = mw * 32 + mt * 16 + (lane >> 2) + half * 8;
            const uint32_t* Ar = g_A + (size_t)smi[r] * 80;
            const uint32_t* Br = g_B + (size_t)sai[r] * 80;
            const uint32_t* Td = g_T + (size_t)sdi[r] * 80;
            const uint32_t* Tg = g_T + (size_t)(9 + sgi[r]) * 80;
            const uint32_t* Ts = g_T + (size_t)(17 + ssi[r]) * 80;
            #pragma unroll
            for (int nt = 0; nt < 5; nt++) {
                int cc = nw * 40 + nt * 8 + (lane & 3) * 2;
                int cw = cc >> 1;
                float2 av = unpack_bf2(Ar[cw]);
                float2 bv = unpack_bf2(Br[cw]);
                float2 dv = unpack_bf2(Td[cw]);
                float2 gv = unpack_bf2(Tg[cw]);
                float2 sv = unpack_bf2(Ts[cw]);
                float x = acc[mt][nt][half * 2]     + av.x + bv.x + dv.x + gv.x + sv.x;
                float y = acc[mt][nt][half * 2 + 1] + av.y + bv.y + dv.y + gv.y + sv.y;
                x = fmaxf(x, 0.f); y = fmaxf(y, 0.f);
                uint32_t w; CVTB2(w, x, y);
                int ch = cc >> 6;
                uint32_t off = Hb + (uint32_t)(ch * 16384) +
                               SWZ((uint32_t)(r * 128 + (cc & 63) * 2));
                STS32(off, w);
            }
        }
    CPW0();
    __syncthreads();

    // ---- layer 2 ----
    #pragma unroll
    for (int i = 0; i < 2; i++)
        #pragma unroll
        for (int j = 0; j < 5; j++)
            #pragma unroll
            for (int k = 0; k < 4; k++) acc[i][j][k] = 0.f;
    #pragma unroll
    for (int ch = 0; ch < 3; ch++)
        mma_chunk40<2>(Hb + ch * 16384, W2b + ch * 20480, (ch == 2) ? 2 : 4,
                       mw * 32, nw * 40, lane, acc);

    // ---- epilogue 2: relu(+b2) . W3 -> reduce -> scores ----
    #pragma unroll
    for (int mt = 0; mt < 2; mt++)
        #pragma unroll
        for (int half = 0; half < 2; half++) {
            float part = 0.f;
            #pragma unroll
            for (int nt = 0; nt < 5; nt++) {
                int cc = nw * 40 + nt * 8 + (lane & 3) * 2;
                float h0 = fmaxf(acc[mt][nt][half * 2]     + s_b2[cc],     0.f);
                float h1 = fmaxf(acc[mt][nt][half * 2 + 1] + s_b2[cc + 1], 0.f);
                part += h0 * s_w3[cc] + h1 * s_w3[cc + 1];
            }
            part += __shfl_xor_sync(0xffffffffu, part, 1);
            part += __shfl_xor_sync(0xffffffffu, part, 2);
            if ((lane & 3) == 0) {
                int r = mw * 32 + mt * 16 + (lane >> 2) + half * 8;
                sred[r][nw] = part;
            }
        }
    __syncthreads();
    if (tid < 128) {
        int p = p0 + tid;
        if (p < P) {
            float s = sred[tid][0] + sred[tid][1] + sred[tid][2] + sred[tid][3]
                    + b3[0] + ms[smi[tid]] + ms[sai[tid]];
            g_scores[p] = s;
        }
    }
}

// ============================================================
__global__ __launch_bounds__(128) void k_softmax(const int* __restrict__ lengths,
                                                 float* __restrict__ out)
{
    int g = blockIdx.x;
    int tid = threadIdx.x;
    int len = lengths[g];
    int st = g_starts[g];
    __shared__ float sm[4], ss[4];

    float v = (tid < len) ? g_scores[st + tid] : -3.4e38f;
    float mx = v;
    #pragma unroll
    for (int o = 16; o > 0; o >>= 1) mx = fmaxf(mx, __shfl_xor_sync(0xffffffffu, mx, o));
    if ((tid & 31) == 0) sm[tid >> 5] = mx;
    __syncthreads();
    mx = fmaxf(fmaxf(sm[0], sm[1]), fmaxf(sm[2], sm[3]));
    mx = fmaxf(mx, 0.f);

    float e = (tid < len) ? expf(v - mx) : 0.f;
    float s = e;
    #pragma unroll
    for (int o = 16; o > 0; o >>= 1) s += __shfl_xor_sync(0xffffffffu, s, o);
    if ((tid & 31) == 0) ss[tid >> 5] = s;
    __syncthreads();

    float epse = expf(-mx);
    float denom = ss[0] + ss[1] + ss[2] + ss[3] + epse;
    float* row = out + (size_t)(g + 1) * GRIDW;
    if (tid < len) row[tid] = e / denom;
    if (tid == 0)  row[len] = epse / denom;
}

// ============================================================
extern "C" void kernel_launch(void* const* d_in, const int* in_sizes, int n_in,
                              void* d_out, int out_size)
{
    const float* gi   = (const float*)d_in[0];
    const float* ms   = (const float*)d_in[1];
    const float* de   = (const float*)d_in[2];
    const float* ge   = (const float*)d_in[3];
    const float* se   = (const float*)d_in[4];
    const float* W1   = (const float*)d_in[5];
    const float* b1   = (const float*)d_in[6];
    const float* W2   = (const float*)d_in[7];
    const float* b2   = (const float*)d_in[8];
    const float* W3   = (const float*)d_in[9];
    const float* b3   = (const float*)d_in[10];
    const int*   mi   = (const int*)d_in[11];
    const int*   ai   = (const int*)d_in[12];
    const int*   di   = (const int*)d_in[13];
    const int*   gidx = (const int*)d_in[14];
    const int*   si   = (const int*)d_in[15];
    const int*   lens = (const int*)d_in[16];
    const int*   segs = (const int*)d_in[17];
    const int*   offs = (const int*)d_in[18];
    float* out = (float*)d_out;

    const int P = in_sizes[11];
    const int M = in_sizes[16];
    const int NSPAN = in_sizes[0] / GDIM;   // 4096

    const int DS = 114688 + 1024;
    static int configured = 0;
    if (!configured) {
        cudaFuncSetAttribute(k_pre,   cudaFuncAttributeMaxDynamicSharedMemorySize, DS);
        cudaFuncSetAttribute(k_fused, cudaFuncAttributeMaxDynamicSharedMemorySize, DS);
        configured = 1;
    }

    long long prep_total = (long long)NSPAN * 512 + (2 * 16 + NCHUNK + 3) * 5120
                         + 20 * 80 + out_size + P;
    k_prep<<<(int)((prep_total + 255) / 256), 256>>>(gi, W1, W2, de, ge, se,
                                                     offs, segs, out,
                                                     NSPAN, P, out_size);

    k_pre<<<dim3(NSPAN / 64, 2), 512, DS>>>(b1);

    int NT = (P + 127) / 128;
    k_fused<<<NT, 512, DS>>>(b2, W3, b3, ms,
                             mi, ai, di, gidx, si, P);

    k_softmax<<<M, 128>>>(lens, out);
}

// round 11
// speedup vs baseline: 1.4209x; 1.0445x over previous
#include <cuda_runtime.h>
#include <cuda_bf16.h>
#include <cstdint>

#define HD 150
#define HP 160
#define GDIM 1000
#define GRIDW 129
#define NCHUNK 16

typedef unsigned long long ull;

// ---------------- helpers ----------------
__device__ __forceinline__ uint32_t smem_u32(const void* p){
    uint32_t a; asm("{ .reg .u64 t; cvta.to.shared.u64 t, %1; cvt.u32.u64 %0, t; }" : "=r"(a) : "l"(p));
    return a;
}
__device__ __forceinline__ uint32_t mul2(uint32_t a, uint32_t b){
    uint32_t r; asm("mul.bf16x2 %0,%1,%2;" : "=r"(r) : "r"(a), "r"(b)); return r;
}
#define CVTB2(res,a,b) asm("cvt.rn.satfinite.bf16x2.f32 %0, %1, %2;" : "=r"(res) : "f"(b), "f"(a))
#define STS128(r0,r1,r2,r3,addr) asm volatile("st.shared.v4.b32 [%0], {%1,%2,%3,%4};" :: "r"(addr), "r"(r0), "r"(r1), "r"(r2), "r"(r3) : "memory")
#define STS32(addr,v) asm volatile("st.shared.b32 [%0], %1;" :: "r"(addr), "r"(v) : "memory")
#define SWZ(a) ((a) ^ (((a)>>3)&0x70))

__device__ __forceinline__ float2 unpack_bf2(uint32_t v){
    float2 r;
    r.x = __uint_as_float(v << 16);
    r.y = __uint_as_float(v & 0xffff0000u);
    return r;
}

#define CPA16(dst,src) asm volatile("cp.async.cg.shared.global [%0], [%1], 16;" :: "r"((uint32_t)(dst)), "l"(src) : "memory")
#define CPC() asm volatile("cp.async.commit_group;" ::: "memory")
#define CPW0() asm volatile("cp.async.wait_group 0;" ::: "memory")
#define CPW1() asm volatile("cp.async.wait_group 1;" ::: "memory")
#define CPW2() asm volatile("cp.async.wait_group 2;" ::: "memory")

#define LDSM4(r0,r1,r2,r3,addr) \
    asm volatile("ldmatrix.sync.aligned.m8n8.x4.shared.b16 {%0,%1,%2,%3}, [%4];" \
        : "=r"(r0),"=r"(r1),"=r"(r2),"=r"(r3) : "r"(addr))
#define LDSM2(r0,r1,addr) \
    asm volatile("ldmatrix.sync.aligned.m8n8.x2.shared.b16 {%0,%1}, [%2];" \
        : "=r"(r0),"=r"(r1) : "r"(addr))

#define MMA(d,a,b) \
    asm volatile("mma.sync.aligned.m16n8k16.row.col.f32.bf16.bf16.f32 " \
        "{%0,%1,%2,%3},{%4,%5,%6,%7},{%8,%9},{%0,%1,%2,%3};" \
        : "+f"((d)[0]),"+f"((d)[1]),"+f"((d)[2]),"+f"((d)[3]) \
        : "r"((a)[0]),"r"((a)[1]),"r"((a)[2]),"r"((a)[3]),"r"((b)[0]),"r"((b)[1]))

// ---------------- scratch ----------------
__device__ uint32_t g_gib[4096 * 512];          // gi as bf16x2, K padded to 1024
__device__ uint32_t g_ABpack[2 * 16 * 5120];    // W1a^T, W1b^T pre-swizzled chunks
__device__ uint32_t g_Bpack[NCHUNK * 5120];     // W1c^T chunks (product block only)
__device__ uint32_t g_B2pack[3 * 5120];         // W2^T chunks
__device__ uint32_t g_A[4096 * 80];             // (gi@W1a + b1) bf16x2
__device__ uint32_t g_B[4096 * 80];             // (gi@W1b) bf16x2
__device__ uint32_t g_T[20 * 80];               // phi tables bf16x2
__device__ float g_scores[132096];
__device__ int   g_starts[2048];

// ============================================================
// warp MMA consumer. TAIL=true: N40 (2xLDSM4 + LDSM2). TAIL=false: N32.
// ============================================================
template<int MT, bool TAIL>
__device__ __forceinline__ void mma_chunk40(uint32_t Ab, uint32_t Bb, int nk16,
                                            int mrow0, int nrow0, int lane,
                                            float (&acc)[MT][5][4])
{
    const int a_row = mrow0 + ((lane>>3)&1)*8 + (lane&7);
    const int a_cb  = (lane>>4)*16;
    const int b_row = nrow0 + ((lane>>4)&1)*8 + (lane&7);
    const int b_cb  = ((lane>>3)&1)*16;
    const int b2_row = nrow0 + 32 + (lane&7);
    const int b2_cb  = ((lane>>3)&1)*16;
    #pragma unroll
    for (int k16 = 0; k16 < nk16; k16++) {
        const int kb = k16 * 32;
        uint32_t a[MT][4];
        #pragma unroll
        for (int mt = 0; mt < MT; mt++) {
            uint32_t ad = Ab + SWZ((uint32_t)((a_row + mt*16)*128 + kb + a_cb));
            LDSM4(a[mt][0], a[mt][1], a[mt][2], a[mt][3], ad);
        }
        uint32_t b[5][2];
        #pragma unroll
        for (int g = 0; g < 2; g++) {
            uint32_t bd = Bb + SWZ((uint32_t)((b_row + g*16)*128 + kb + b_cb));
            uint32_t r0, r1, r2, r3;
            LDSM4(r0, r1, r2, r3, bd);
            b[2*g][0] = r0; b[2*g][1] = r1; b[2*g+1][0] = r2; b[2*g+1][1] = r3;
        }
        if constexpr (TAIL) {
            uint32_t bd = Bb + SWZ((uint32_t)(b2_row*128 + kb + b2_cb));
            LDSM2(b[4][0], b[4][1], bd);
        }
        #pragma unroll
        for (int mt = 0; mt < MT; mt++)
            #pragma unroll
            for (int nt = 0; nt < (TAIL ? 5 : 4); nt++)
                MMA(acc[mt][nt], a[mt], b[nt]);
    }
}

// ============================================================
// prep (fused: packs + phi tables + fill + starts)
// ============================================================
__global__ void k_prep(const float* __restrict__ gi, const float* __restrict__ W1,
                       const float* __restrict__ W2,
                       const float* __restrict__ de, const float* __restrict__ ge,
                       const float* __restrict__ se,
                       const int* __restrict__ offs, const int* __restrict__ segs,
                       float* __restrict__ out, int NSPAN, int P, int out_total)
{
    long long idx = (long long)blockIdx.x * 256 + threadIdx.x;
    const long long NG  = (long long)NSPAN * 512;
    const long long AB  = NG + 2 * 16 * 5120;
    const long long BP  = AB + NCHUNK * 5120;
    const long long B2E = BP + 3 * 5120;
    const long long TE  = B2E + 20 * 80;
    const long long FE  = TE + out_total;
    const long long SE  = FE + P;
    if (idx < NG) {
        int n = (int)(idx >> 9), kw = (int)(idx & 511);
        int c0 = kw * 2;
        float a = (c0     < GDIM) ? gi[(size_t)n * GDIM + c0]     : 0.f;
        float b = (c0 + 1 < GDIM) ? gi[(size_t)n * GDIM + c0 + 1] : 0.f;
        uint32_t w; CVTB2(w, a, b);
        g_gib[idx] = w;
    } else if (idx < AB) {
        int t = (int)(idx - NG);
        int sel = t / (16 * 5120); int rem = t - sel * 16 * 5120;
        int c = rem / 5120, r = rem % 5120;
        int n = r >> 5, kk = (r & 31) * 2;
        int kg = c * 64 + kk;
        float v0 = 0.f, v1 = 0.f;
        if (n < HD) {
            if (kg     < GDIM) v0 = W1[(size_t)(sel * GDIM + kg)     * HD + n];
            if (kg + 1 < GDIM) v1 = W1[(size_t)(sel * GDIM + kg + 1) * HD + n];
        }
        uint32_t w; CVTB2(w, v0, v1);
        uint32_t off = (uint32_t)(n * 128 + kk * 2);
        g_ABpack[(sel * 16 + c) * 5120 + (SWZ(off) >> 2)] = w;
    } else if (idx < BP) {
        int t = (int)(idx - AB);
        int c = t / 5120, r = t % 5120;
        int n = r >> 5, kk = (r & 31) * 2;
        int kg = c * 64 + kk;
        float v0 = 0.f, v1 = 0.f;
        if (n < HD) {
            if (kg     < GDIM) v0 = W1[(size_t)(2000 + kg) * HD + n];
            if (kg + 1 < GDIM) v1 = W1[(size_t)(2001 + kg) * HD + n];
        }
        uint32_t w; CVTB2(w, v0, v1);
        uint32_t off = (uint32_t)(n * 128 + kk * 2);
        g_Bpack[c * 5120 + (SWZ(off) >> 2)] = w;
    } else if (idx < B2E) {
        int t = (int)(idx - BP);
        int c = t / 5120, r = t % 5120;
        int n = r >> 5, kk = (r & 31) * 2;
        int kg = c * 64 + kk;
        float v0 = 0.f, v1 = 0.f;
        if (n < HD) {
            if (kg     < HD) v0 = W2[(size_t)kg       * HD + n];
            if (kg + 1 < HD) v1 = W2[(size_t)(kg + 1) * HD + n];
        }
        uint32_t w; CVTB2(w, v0, v1);
        uint32_t off = (uint32_t)(n * 128 + kk * 2);
        g_B2pack[c * 5120 + (SWZ(off) >> 2)] = w;
    } else if (idx < TE) {
        int t = (int)(idx - B2E);
        int r = t / 80, cc = (t % 80) * 2;
        const float* emb; int wbase;
        if (r < 9)       { emb = de + r * 20;        wbase = 3000; }
        else if (r < 17) { emb = ge + (r - 9) * 20;  wbase = 3020; }
        else             { emb = se + (r - 17) * 20; wbase = 3040; }
        float v0 = 0.f, v1 = 0.f;
        if (cc < HD) {
            for (int k = 0; k < 20; k++) {
                float e = emb[k];
                v0 += e * W1[(size_t)(wbase + k) * HD + cc];
                if (cc + 1 < HD) v1 += e * W1[(size_t)(wbase + k) * HD + cc + 1];
            }
        }
        uint32_t w; CVTB2(w, v0, v1);
        g_T[r * 80 + (cc >> 1)] = w;
    } else if (idx < FE) {
        long long i = idx - TE;
        out[i] = (i == 0) ? 1.0f : 1000.0f;
    } else if (idx < SE) {
        int p = (int)(idx - FE);
        if (offs[p] == 0) g_starts[segs[p]] = p;
    }
}

// ============================================================
// k_pre: g_A = (gi @ W1a) + b1, g_B = gi @ W1b   (bf16x2 output)
// N-trim: nw==3 skips dead cols 152..159. K-trim: chunk15 nk16=3.
// ============================================================
__global__ __launch_bounds__(512) void k_pre(const float* __restrict__ b1)
{
    extern __shared__ char dsm[];
    const int tid = threadIdx.x;
    const int lane = tid & 31;
    const int wid = tid >> 5;
    const int mw = wid & 3, nw = wid >> 2;
    const int n0 = blockIdx.x * 64;
    const int sel = blockIdx.y;

    uint32_t rbase = (smem_u32(dsm) + 1023u) & ~1023u;
    const char* Bsrc = (const char*)(g_ABpack + sel * 16 * 5120);

    float acc[1][5][4];
    #pragma unroll
    for (int j = 0; j < 5; j++)
        #pragma unroll
        for (int k = 0; k < 4; k++) acc[0][j][k] = 0.f;

    auto issue = [&](int c) {
        int s = c & 3;
        uint32_t Ab = rbase + (uint32_t)(s * 8192);
        uint32_t Bb = rbase + 32768u + (uint32_t)(s * 20480);
        {
            int row = tid >> 3, seg = tid & 7;
            const char* src = (const char*)g_gib + ((size_t)(n0 + row) * 2048 + c * 128 + seg * 16);
            CPA16(Ab + SWZ((uint32_t)(row * 128 + seg * 16)), src);
        }
        #pragma unroll
        for (int t = 0; t < 3; t++) {
            int j = tid + t * 512;
            if (j < 1280) CPA16(Bb + (uint32_t)(j * 16), Bsrc + (size_t)c * 20480 + j * 16);
        }
        CPC();
    };

    issue(0); issue(1); issue(2);
    for (int c = 0; c < 16; c++) {
        if (c <= 13) CPW2(); else if (c == 14) CPW1(); else CPW0();
        __syncthreads();
        if (c + 3 < 16) issue(c + 3);
        int s = c & 3;
        int nk = (c == 15) ? 3 : 4;
        uint32_t Ab = rbase + (uint32_t)(s * 8192);
        uint32_t Bb = rbase + 32768u + (uint32_t)(s * 20480);
        if (nw < 3) mma_chunk40<1,true >(Ab, Bb, nk, mw * 16, nw * 40, lane, acc);
        else        mma_chunk40<1,false>(Ab, Bb, nk, mw * 16, nw * 40, lane, acc);
    }

    uint32_t* dst = sel ? g_B : g_A;
    #pragma unroll
    for (int half = 0; half < 2; half++) {
        int row = n0 + mw * 16 + (lane >> 2) + half * 8;
        #pragma unroll
        for (int nt = 0; nt < 5; nt++) {
            if (nw == 3 && nt == 4) continue;     // dead cols 152..159
            int cc = nw * 40 + nt * 8 + (lane & 3) * 2;
            float x = acc[0][nt][half * 2];
            float y = acc[0][nt][half * 2 + 1];
            if (!sel) {
                if (cc     < HD) x += b1[cc];
                if (cc + 1 < HD) y += b1[cc + 1];
            }
            uint32_t w; CVTB2(w, x, y);
            dst[(size_t)row * 80 + (cc >> 1)] = w;
        }
    }
}

// ============================================================
// fused pair kernel: layer1 HMMA (product only) + relu(+tables) + layer2 + score
// N-trim (nw==3) and K-trim (chunk15 nk16=3) applied.
// ============================================================
__global__ __launch_bounds__(512) void k_fused(
    const float* __restrict__ b2,
    const float* __restrict__ W3, const float* __restrict__ b3,
    const float* __restrict__ ms,
    const int* __restrict__ mi, const int* __restrict__ ai,
    const int* __restrict__ di, const int* __restrict__ gx, const int* __restrict__ si,
    int P)
{
    extern __shared__ char dsm[];
    __shared__ int smi[128], sai[128], sdi[128], sgi[128], ssi[128];
    __shared__ __align__(16) float s_b2[HP], s_w3[HP];
    __shared__ float sred[128][4];

    const int tid = threadIdx.x;
    const int lane = tid & 31;
    const int wid = tid >> 5;
    const int mw = wid & 3, nw = wid >> 2;
    const int p0 = blockIdx.x * 128;

    uint32_t rbase = (smem_u32(dsm) + 1023u) & ~1023u;
    const uint32_t Hb  = rbase;
    const uint32_t W2b = rbase + 53248u;

    if (tid < 128) {
        int p = p0 + tid; if (p >= P) p = P - 1;
        smi[tid] = mi[p]; sai[tid] = ai[p];
        sdi[tid] = di[p]; sgi[tid] = gx[p]; ssi[tid] = si[p];
    }
    if (tid >= 256 && tid < 256 + HP) {
        int h = tid - 256;
        s_b2[h] = (h < HD) ? b2[h] : 0.f;
        s_w3[h] = (h < HD) ? W3[h] : 0.f;
    }
    __syncthreads();

    float acc[2][5][4];
    #pragma unroll
    for (int i = 0; i < 2; i++)
        #pragma unroll
        for (int j = 0; j < 5; j++)
            #pragma unroll
            for (int k = 0; k < 4; k++) acc[i][j][k] = 0.f;

    const int m = tid >> 2, q = tid & 3;

    uint4 iA[2], jA[2];
    auto loadA = [&](int c) {
        const uint4* Ip = ((const uint4*)g_gib) + ((size_t)smi[m] * 128 + c * 8 + q * 2);
        const uint4* Jp = ((const uint4*)g_gib) + ((size_t)sai[m] * 128 + c * 8 + q * 2);
        iA[0] = Ip[0]; iA[1] = Ip[1];
        jA[0] = Jp[0]; jA[1] = Jp[1];
    };
    auto storeA = [&](int c) {
        uint32_t asb = rbase + (uint32_t)((c & 1) * 16384) + (uint32_t)(m * 128 + q * 32);
        #pragma unroll
        for (int t = 0; t < 2; t++) {
            uint4 r;
            r.x = mul2(iA[t].x, jA[t].x); r.y = mul2(iA[t].y, jA[t].y);
            r.z = mul2(iA[t].z, jA[t].z); r.w = mul2(iA[t].w, jA[t].w);
            STS128(r.x, r.y, r.z, r.w, SWZ(asb + t * 16));
        }
    };
    auto issueB = [&](int c) {
        uint32_t Bb = rbase + 32768u + (uint32_t)((c & 3) * 20480);
        const char* src = (const char*)(g_Bpack + c * 5120);
        #pragma unroll
        for (int t = 0; t < 3; t++) {
            int i = tid + t * 512;
            if (i < 1280) CPA16(Bb + (uint32_t)(i * 16), src + (size_t)i * 16);
        }
        CPC();
    };

    // ---- layer 1 pipeline: B 3 chunks ahead, 1 barrier/chunk ----
    issueB(0); issueB(1); issueB(2);
    loadA(0);
    storeA(0);
    for (int c = 0; c < NCHUNK; c++) {
        if (c + 1 < NCHUNK) loadA(c + 1);
        if (c < NCHUNK - 2) CPW2(); else if (c == NCHUNK - 2) CPW1(); else CPW0();
        __syncthreads();
        if (c + 3 < NCHUNK) issueB(c + 3);
        int s = c & 3;
        int nk = (c == NCHUNK - 1) ? 3 : 4;
        uint32_t Ab = rbase + (uint32_t)((c & 1) * 16384);
        uint32_t Bb = rbase + 32768u + (uint32_t)(s * 20480);
        if (nw < 3) mma_chunk40<2,true >(Ab, Bb, nk, mw * 32, nw * 40, lane, acc);
        else        mma_chunk40<2,false>(Ab, Bb, nk, mw * 32, nw * 40, lane, acc);
        if (c + 1 < NCHUNK) storeA(c + 1);
    }
    __syncthreads();   // all MMA reads done before H/W2 overwrite A/B regions

    // ---- W2^T cp.async ----
    {
        const char* src = (const char*)g_B2pack;
        #pragma unroll
        for (int t = 0; t < 8; t++) {
            int i = tid + t * 512;
            if (i < 3840) CPA16(W2b + (uint32_t)(i * 16), src + (size_t)i * 16);
        }
        CPC();
    }

    // ---- epilogue 1: +(A[mi]+b1)+(B[ai])+phi tables, relu -> bf16 H tile ----
    #pragma unroll
    for (int mt = 0; mt < 2; mt++)
        #pragma unroll
        for (int half = 0; half < 2; half++) {
            int r = mw * 32 + mt * 16 + (lane >> 2) + half * 8;
            const uint32_t* Ar = g_A + (size_t)smi[r] * 80;
            const uint32_t* Br = g_B + (size_t)sai[r] * 80;
            const uint32_t* Td = g_T + (size_t)sdi[r] * 80;
            const uint32_t* Tg = g_T + (size_t)(9 + sgi[r]) * 80;
            const uint32_t* Ts = g_T + (size_t)(17 + ssi[r]) * 80;
            #pragma unroll
            for (int nt = 0; nt < 5; nt++) {
                if (nw == 3 && nt == 4) continue;   // dead cols 152..159 (x0 weights)
                int cc = nw * 40 + nt * 8 + (lane & 3) * 2;
                int cw = cc >> 1;
                float2 av = unpack_bf2(Ar[cw]);
                float2 bv = unpack_bf2(Br[cw]);
                float2 dv = unpack_bf2(Td[cw]);
                float2 gv = unpack_bf2(Tg[cw]);
                float2 sv = unpack_bf2(Ts[cw]);
                float x = acc[mt][nt][half * 2]     + av.x + bv.x + dv.x + gv.x + sv.x;
                float y = acc[mt][nt][half * 2 + 1] + av.y + bv.y + dv.y + gv.y + sv.y;
                x = fmaxf(x, 0.f); y = fmaxf(y, 0.f);
                uint32_t w; CVTB2(w, x, y);
                int ch = cc >> 6;
                uint32_t off = Hb + (uint32_t)(ch * 16384) +
                               SWZ((uint32_t)(r * 128 + (cc & 63) * 2));
                STS32(off, w);
            }
        }
    CPW0();
    __syncthreads();

    // ---- layer 2 ----
    #pragma unroll
    for (int i = 0; i < 2; i++)
        #pragma unroll
        for (int j = 0; j < 5; j++)
            #pragma unroll
            for (int k = 0; k < 4; k++) acc[i][j][k] = 0.f;
    #pragma unroll
    for (int ch = 0; ch < 3; ch++) {
        int nk = (ch == 2) ? 2 : 4;
        if (nw < 3) mma_chunk40<2,true >(Hb + ch * 16384, W2b + ch * 20480, nk, mw * 32, nw * 40, lane, acc);
        else        mma_chunk40<2,false>(Hb + ch * 16384, W2b + ch * 20480, nk, mw * 32, nw * 40, lane, acc);
    }

    // ---- epilogue 2: relu(+b2) . W3 -> reduce -> scores ----
    // (nw==3 nt==4 accumulators are zero-init and untouched; s_b2/s_w3 zero there)
    #pragma unroll
    for (int mt = 0; mt < 2; mt++)
        #pragma unroll
        for (int half = 0; half < 2; half++) {
            float part = 0.f;
            #pragma unroll
            for (int nt = 0; nt < 5; nt++) {
                int cc = nw * 40 + nt * 8 + (lane & 3) * 2;
                float h0 = fmaxf(acc[mt][nt][half * 2]     + s_b2[cc],     0.f);
                float h1 = fmaxf(acc[mt][nt][half * 2 + 1] + s_b2[cc + 1], 0.f);
                part += h0 * s_w3[cc] + h1 * s_w3[cc + 1];
            }
            part += __shfl_xor_sync(0xffffffffu, part, 1);
            part += __shfl_xor_sync(0xffffffffu, part, 2);
            if ((lane & 3) == 0) {
                int r = mw * 32 + mt * 16 + (lane >> 2) + half * 8;
                sred[r][nw] = part;
            }
        }
    __syncthreads();
    if (tid < 128) {
        int p = p0 + tid;
        if (p < P) {
            float s = sred[tid][0] + sred[tid][1] + sred[tid][2] + sred[tid][3]
                    + b3[0] + ms[smi[tid]] + ms[sai[tid]];
            g_scores[p] = s;
        }
    }
}

// ============================================================
__global__ __launch_bounds__(128) void k_softmax(const int* __restrict__ lengths,
                                                 float* __restrict__ out)
{
    int g = blockIdx.x;
    int tid = threadIdx.x;
    int len = lengths[g];
    int st = g_starts[g];
    __shared__ float sm[4], ss[4];

    float v = (tid < len) ? g_scores[st + tid] : -3.4e38f;
    float mx = v;
    #pragma unroll
    for (int o = 16; o > 0; o >>= 1) mx = fmaxf(mx, __shfl_xor_sync(0xffffffffu, mx, o));
    if ((tid & 31) == 0) sm[tid >> 5] = mx;
    __syncthreads();
    mx = fmaxf(fmaxf(sm[0], sm[1]), fmaxf(sm[2], sm[3]));
    mx = fmaxf(mx, 0.f);

    float e = (tid < len) ? expf(v - mx) : 0.f;
    float s = e;
    #pragma unroll
    for (int o = 16; o > 0; o >>= 1) s += __shfl_xor_sync(0xffffffffu, s, o);
    if ((tid & 31) == 0) ss[tid >> 5] = s;
    __syncthreads();

    float epse = expf(-mx);
    float denom = ss[0] + ss[1] + ss[2] + ss[3] + epse;
    float* row = out + (size_t)(g + 1) * GRIDW;
    if (tid < len) row[tid] = e / denom;
    if (tid == 0)  row[len] = epse / denom;
}

// ============================================================
extern "C" void kernel_launch(void* const* d_in, const int* in_sizes, int n_in,
                              void* d_out, int out_size)
{
    const float* gi   = (const float*)d_in[0];
    const float* ms   = (const float*)d_in[1];
    const float* de   = (const float*)d_in[2];
    const float* ge   = (const float*)d_in[3];
    const float* se   = (const float*)d_in[4];
    const float* W1   = (const float*)d_in[5];
    const float* b1   = (const float*)d_in[6];
    const float* W2   = (const float*)d_in[7];
    const float* b2   = (const float*)d_in[8];
    const float* W3   = (const float*)d_in[9];
    const float* b3   = (const float*)d_in[10];
    const int*   mi   = (const int*)d_in[11];
    const int*   ai   = (const int*)d_in[12];
    const int*   di   = (const int*)d_in[13];
    const int*   gidx = (const int*)d_in[14];
    const int*   si   = (const int*)d_in[15];
    const int*   lens = (const int*)d_in[16];
    const int*   segs = (const int*)d_in[17];
    const int*   offs = (const int*)d_in[18];
    float* out = (float*)d_out;

    const int P = in_sizes[11];
    const int M = in_sizes[16];
    const int NSPAN = in_sizes[0] / GDIM;   // 4096

    const int DS = 114688 + 1024;
    static int configured = 0;
    if (!configured) {
        cudaFuncSetAttribute(k_pre,   cudaFuncAttributeMaxDynamicSharedMemorySize, DS);
        cudaFuncSetAttribute(k_fused, cudaFuncAttributeMaxDynamicSharedMemorySize, DS);
        configured = 1;
    }

    long long prep_total = (long long)NSPAN * 512 + (2 * 16 + NCHUNK + 3) * 5120
                         + 20 * 80 + out_size + P;
    k_prep<<<(int)((prep_total + 255) / 256), 256>>>(gi, W1, W2, de, ge, se,
                                                     offs, segs, out,
                                                     NSPAN, P, out_size);

    k_pre<<<dim3(NSPAN / 64, 2), 512, DS>>>(b1);

    int NT = (P + 127) / 128;
    k_fused<<<NT, 512, DS>>>(b2, W3, b3, ms,
                             mi, ai, di, gidx, si, P);

    k_softmax<<<M, 128>>>(lens, out);
}

// round 12
// speedup vs baseline: 1.4468x; 1.0182x over previous
#include <cuda_runtime.h>
#include <cuda_bf16.h>
#include <cstdint>

#define HD 150
#define HP 160
#define GDIM 1000
#define GRIDW 129
#define NCHUNK 16

typedef unsigned long long ull;

// ---------------- helpers ----------------
__device__ __forceinline__ uint32_t smem_u32(const void* p){
    uint32_t a; asm("{ .reg .u64 t; cvta.to.shared.u64 t, %1; cvt.u32.u64 %0, t; }" : "=r"(a) : "l"(p));
    return a;
}
__device__ __forceinline__ uint32_t mul2(uint32_t a, uint32_t b){
    uint32_t r; asm("mul.bf16x2 %0,%1,%2;" : "=r"(r) : "r"(a), "r"(b)); return r;
}
#define CVTB2(res,a,b) asm("cvt.rn.satfinite.bf16x2.f32 %0, %1, %2;" : "=r"(res) : "f"(b), "f"(a))
#define STS128(r0,r1,r2,r3,addr) asm volatile("st.shared.v4.b32 [%0], {%1,%2,%3,%4};" :: "r"(addr), "r"(r0), "r"(r1), "r"(r2), "r"(r3) : "memory")
#define LDS128(r0,r1,r2,r3,addr) asm volatile("ld.shared.v4.b32 {%0,%1,%2,%3}, [%4];" : "=r"(r0),"=r"(r1),"=r"(r2),"=r"(r3) : "r"(addr))
#define STS32(addr,v) asm volatile("st.shared.b32 [%0], %1;" :: "r"(addr), "r"(v) : "memory")
#define SWZ(a) ((a) ^ (((a)>>3)&0x70))

__device__ __forceinline__ float2 unpack_bf2(uint32_t v){
    float2 r;
    r.x = __uint_as_float(v << 16);
    r.y = __uint_as_float(v & 0xffff0000u);
    return r;
}

#define CPA16(dst,src) asm volatile("cp.async.cg.shared.global [%0], [%1], 16;" :: "r"((uint32_t)(dst)), "l"(src) : "memory")
#define CPC() asm volatile("cp.async.commit_group;" ::: "memory")
#define CPW0() asm volatile("cp.async.wait_group 0;" ::: "memory")
#define CPW1() asm volatile("cp.async.wait_group 1;" ::: "memory")
#define CPW2() asm volatile("cp.async.wait_group 2;" ::: "memory")

#define LDSM4(r0,r1,r2,r3,addr) \
    asm volatile("ldmatrix.sync.aligned.m8n8.x4.shared.b16 {%0,%1,%2,%3}, [%4];" \
        : "=r"(r0),"=r"(r1),"=r"(r2),"=r"(r3) : "r"(addr))
#define LDSM2(r0,r1,addr) \
    asm volatile("ldmatrix.sync.aligned.m8n8.x2.shared.b16 {%0,%1}, [%2];" \
        : "=r"(r0),"=r"(r1) : "r"(addr))

#define MMA(d,a,b) \
    asm volatile("mma.sync.aligned.m16n8k16.row.col.f32.bf16.bf16.f32 " \
        "{%0,%1,%2,%3},{%4,%5,%6,%7},{%8,%9},{%0,%1,%2,%3};" \
        : "+f"((d)[0]),"+f"((d)[1]),"+f"((d)[2]),"+f"((d)[3]) \
        : "r"((a)[0]),"r"((a)[1]),"r"((a)[2]),"r"((a)[3]),"r"((b)[0]),"r"((b)[1]))

// ---------------- scratch ----------------
__device__ uint32_t g_gib[4096 * 512];          // gi as bf16x2, K padded to 1024
__device__ uint32_t g_ABpack[2 * 16 * 5120];    // W1a^T, W1b^T pre-swizzled chunks
__device__ uint32_t g_Bpack[NCHUNK * 5120];     // W1c^T chunks
__device__ uint32_t g_B2pack[3 * 5120];         // W2^T chunks
__device__ uint32_t g_A[4096 * 80];             // (gi@W1a + b1) bf16x2 (full 160 cols)
__device__ uint32_t g_B[4096 * 80];             // (gi@W1b) bf16x2
__device__ uint32_t g_T[216 * 80];              // combined phi tables bf16x2 (d*24+g*3+s)
__device__ float g_scores[132096];
__device__ int   g_starts[2048];

// ============================================================
// warp MMA consumer. TAIL=true: N40 (2xLDSM4 + LDSM2). TAIL=false: N32.
// ============================================================
template<int MT, bool TAIL>
__device__ __forceinline__ void mma_chunk40(uint32_t Ab, uint32_t Bb, int nk16,
                                            int mrow0, int nrow0, int lane,
                                            float (&acc)[MT][5][4])
{
    const int a_row = mrow0 + ((lane>>3)&1)*8 + (lane&7);
    const int a_cb  = (lane>>4)*16;
    const int b_row = nrow0 + ((lane>>4)&1)*8 + (lane&7);
    const int b_cb  = ((lane>>3)&1)*16;
    const int b2_row = nrow0 + 32 + (lane&7);
    const int b2_cb  = ((lane>>3)&1)*16;
    #pragma unroll
    for (int k16 = 0; k16 < nk16; k16++) {
        const int kb = k16 * 32;
        uint32_t a[MT][4];
        #pragma unroll
        for (int mt = 0; mt < MT; mt++) {
            uint32_t ad = Ab + SWZ((uint32_t)((a_row + mt*16)*128 + kb + a_cb));
            LDSM4(a[mt][0], a[mt][1], a[mt][2], a[mt][3], ad);
        }
        uint32_t b[5][2];
        #pragma unroll
        for (int g = 0; g < 2; g++) {
            uint32_t bd = Bb + SWZ((uint32_t)((b_row + g*16)*128 + kb + b_cb));
            uint32_t r0, r1, r2, r3;
            LDSM4(r0, r1, r2, r3, bd);
            b[2*g][0] = r0; b[2*g][1] = r1; b[2*g+1][0] = r2; b[2*g+1][1] = r3;
        }
        if constexpr (TAIL) {
            uint32_t bd = Bb + SWZ((uint32_t)(b2_row*128 + kb + b2_cb));
            LDSM2(b[4][0], b[4][1], bd);
        }
        #pragma unroll
        for (int mt = 0; mt < MT; mt++)
            #pragma unroll
            for (int nt = 0; nt < (TAIL ? 5 : 4); nt++)
                MMA(acc[mt][nt], a[mt], b[nt]);
    }
}

// ============================================================
// prep (fused: packs + combined phi tables + fill + starts)
// ============================================================
__global__ void k_prep(const float* __restrict__ gi, const float* __restrict__ W1,
                       const float* __restrict__ W2,
                       const float* __restrict__ de, const float* __restrict__ ge,
                       const float* __restrict__ se,
                       const int* __restrict__ offs, const int* __restrict__ segs,
                       float* __restrict__ out, int NSPAN, int P, int out_total)
{
    long long idx = (long long)blockIdx.x * 256 + threadIdx.x;
    const long long NG  = (long long)NSPAN * 512;
    const long long AB  = NG + 2 * 16 * 5120;
    const long long BP  = AB + NCHUNK * 5120;
    const long long B2E = BP + 3 * 5120;
    const long long TE  = B2E + 216 * 80;
    const long long FE  = TE + out_total;
    const long long SE  = FE + P;
    if (idx < NG) {
        int n = (int)(idx >> 9), kw = (int)(idx & 511);
        int c0 = kw * 2;
        float a = (c0     < GDIM) ? gi[(size_t)n * GDIM + c0]     : 0.f;
        float b = (c0 + 1 < GDIM) ? gi[(size_t)n * GDIM + c0 + 1] : 0.f;
        uint32_t w; CVTB2(w, a, b);
        g_gib[idx] = w;
    } else if (idx < AB) {
        int t = (int)(idx - NG);
        int sel = t / (16 * 5120); int rem = t - sel * 16 * 5120;
        int c = rem / 5120, r = rem % 5120;
        int n = r >> 5, kk = (r & 31) * 2;
        int kg = c * 64 + kk;
        float v0 = 0.f, v1 = 0.f;
        if (n < HD) {
            if (kg     < GDIM) v0 = W1[(size_t)(sel * GDIM + kg)     * HD + n];
            if (kg + 1 < GDIM) v1 = W1[(size_t)(sel * GDIM + kg + 1) * HD + n];
        }
        uint32_t w; CVTB2(w, v0, v1);
        uint32_t off = (uint32_t)(n * 128 + kk * 2);
        g_ABpack[(sel * 16 + c) * 5120 + (SWZ(off) >> 2)] = w;
    } else if (idx < BP) {
        int t = (int)(idx - AB);
        int c = t / 5120, r = t % 5120;
        int n = r >> 5, kk = (r & 31) * 2;
        int kg = c * 64 + kk;
        float v0 = 0.f, v1 = 0.f;
        if (n < HD) {
            if (kg     < GDIM) v0 = W1[(size_t)(2000 + kg) * HD + n];
            if (kg + 1 < GDIM) v1 = W1[(size_t)(2001 + kg) * HD + n];
        }
        uint32_t w; CVTB2(w, v0, v1);
        uint32_t off = (uint32_t)(n * 128 + kk * 2);
        g_Bpack[c * 5120 + (SWZ(off) >> 2)] = w;
    } else if (idx < B2E) {
        int t = (int)(idx - BP);
        int c = t / 5120, r = t % 5120;
        int n = r >> 5, kk = (r & 31) * 2;
        int kg = c * 64 + kk;
        float v0 = 0.f, v1 = 0.f;
        if (n < HD) {
            if (kg     < HD) v0 = W2[(size_t)kg       * HD + n];
            if (kg + 1 < HD) v1 = W2[(size_t)(kg + 1) * HD + n];
        }
        uint32_t w; CVTB2(w, v0, v1);
        uint32_t off = (uint32_t)(n * 128 + kk * 2);
        g_B2pack[c * 5120 + (SWZ(off) >> 2)] = w;
    } else if (idx < TE) {
        // combined phi table: row r = d*24 + g*3 + s
        int t = (int)(idx - B2E);
        int r = t / 80, cc = (t % 80) * 2;
        int d = r / 24, rem = r % 24;
        int g = rem / 3, s = rem % 3;
        float v0 = 0.f, v1 = 0.f;
        if (cc < HD) {
            for (int k = 0; k < 20; k++) {
                float ed = de[d * 20 + k], eg = ge[g * 20 + k], es = se[s * 20 + k];
                v0 += ed * W1[(size_t)(3000 + k) * HD + cc]
                    + eg * W1[(size_t)(3020 + k) * HD + cc]
                    + es * W1[(size_t)(3040 + k) * HD + cc];
                if (cc + 1 < HD)
                    v1 += ed * W1[(size_t)(3000 + k) * HD + cc + 1]
                        + eg * W1[(size_t)(3020 + k) * HD + cc + 1]
                        + es * W1[(size_t)(3040 + k) * HD + cc + 1];
            }
        }
        uint32_t w; CVTB2(w, v0, v1);
        g_T[r * 80 + (cc >> 1)] = w;
    } else if (idx < FE) {
        long long i = idx - TE;
        out[i] = (i == 0) ? 1.0f : 1000.0f;
    } else if (idx < SE) {
        int p = (int)(idx - FE);
        if (offs[p] == 0) g_starts[segs[p]] = p;
    }
}

// ============================================================
// k_pre: g_A = (gi @ W1a) + b1, g_B = gi @ W1b   (bf16x2 output, full 160 cols)
// MMA N-trim for nw==3 nt==4 (acc stays 0 -> stores zeros). K-trim chunk15.
// ============================================================
__global__ __launch_bounds__(512) void k_pre(const float* __restrict__ b1)
{
    extern __shared__ char dsm[];
    const int tid = threadIdx.x;
    const int lane = tid & 31;
    const int wid = tid >> 5;
    const int mw = wid & 3, nw = wid >> 2;
    const int n0 = blockIdx.x * 64;
    const int sel = blockIdx.y;

    uint32_t rbase = (smem_u32(dsm) + 1023u) & ~1023u;
    const char* Bsrc = (const char*)(g_ABpack + sel * 16 * 5120);

    float acc[1][5][4];
    #pragma unroll
    for (int j = 0; j < 5; j++)
        #pragma unroll
        for (int k = 0; k < 4; k++) acc[0][j][k] = 0.f;

    auto issue = [&](int c) {
        int s = c & 3;
        uint32_t Ab = rbase + (uint32_t)(s * 8192);
        uint32_t Bb = rbase + 32768u + (uint32_t)(s * 20480);
        {
            int row = tid >> 3, seg = tid & 7;
            const char* src = (const char*)g_gib + ((size_t)(n0 + row) * 2048 + c * 128 + seg * 16);
            CPA16(Ab + SWZ((uint32_t)(row * 128 + seg * 16)), src);
        }
        #pragma unroll
        for (int t = 0; t < 3; t++) {
            int j = tid + t * 512;
            if (j < 1280) CPA16(Bb + (uint32_t)(j * 16), Bsrc + (size_t)c * 20480 + j * 16);
        }
        CPC();
    };

    issue(0); issue(1); issue(2);
    for (int c = 0; c < 16; c++) {
        if (c <= 13) CPW2(); else if (c == 14) CPW1(); else CPW0();
        __syncthreads();
        if (c + 3 < 16) issue(c + 3);
        int s = c & 3;
        int nk = (c == 15) ? 3 : 4;
        uint32_t Ab = rbase + (uint32_t)(s * 8192);
        uint32_t Bb = rbase + 32768u + (uint32_t)(s * 20480);
        if (nw < 3) mma_chunk40<1,true >(Ab, Bb, nk, mw * 16, nw * 40, lane, acc);
        else        mma_chunk40<1,false>(Ab, Bb, nk, mw * 16, nw * 40, lane, acc);
    }

    uint32_t* dst = sel ? g_B : g_A;
    #pragma unroll
    for (int half = 0; half < 2; half++) {
        int row = n0 + mw * 16 + (lane >> 2) + half * 8;
        #pragma unroll
        for (int nt = 0; nt < 5; nt++) {
            int cc = nw * 40 + nt * 8 + (lane & 3) * 2;
            float x = acc[0][nt][half * 2];
            float y = acc[0][nt][half * 2 + 1];
            if (!sel) {
                if (cc     < HD) x += b1[cc];
                if (cc + 1 < HD) y += b1[cc + 1];
            }
            uint32_t w; CVTB2(w, x, y);
            dst[(size_t)row * 80 + (cc >> 1)] = w;
        }
    }
}

// ============================================================
// fused pair kernel: layer1 HMMA + two-pass epilogue(+tables) + layer2 + score
// ============================================================
__global__ __launch_bounds__(512) void k_fused(
    const float* __restrict__ b2,
    const float* __restrict__ W3, const float* __restrict__ b3,
    const float* __restrict__ ms,
    const int* __restrict__ mi, const int* __restrict__ ai,
    const int* __restrict__ di, const int* __restrict__ gx, const int* __restrict__ si,
    int P)
{
    extern __shared__ char dsm[];
    __shared__ int smi[128], sai[128], sti[128];
    __shared__ __align__(16) float s_b2[HP], s_w3[HP];
    __shared__ float sred[128][4];

    const int tid = threadIdx.x;
    const int lane = tid & 31;
    const int wid = tid >> 5;
    const int mw = wid & 3, nw = wid >> 2;
    const int p0 = blockIdx.x * 128;

    uint32_t rbase = (smem_u32(dsm) + 1023u) & ~1023u;
    const uint32_t Hb  = rbase;
    const uint32_t W2b = rbase + 53248u;

    if (tid < 128) {
        int p = p0 + tid; if (p >= P) p = P - 1;
        smi[tid] = mi[p]; sai[tid] = ai[p];
        sti[tid] = di[p] * 24 + gx[p] * 3 + si[p];
    }
    if (tid >= 256 && tid < 256 + HP) {
        int h = tid - 256;
        s_b2[h] = (h < HD) ? b2[h] : 0.f;
        s_w3[h] = (h < HD) ? W3[h] : 0.f;
    }
    __syncthreads();

    float acc[2][5][4];
    #pragma unroll
    for (int i = 0; i < 2; i++)
        #pragma unroll
        for (int j = 0; j < 5; j++)
            #pragma unroll
            for (int k = 0; k < 4; k++) acc[i][j][k] = 0.f;

    const int m = tid >> 2, q = tid & 3;

    uint4 iA[2], jA[2];
    auto loadA = [&](int c) {
        const uint4* Ip = ((const uint4*)g_gib) + ((size_t)smi[m] * 128 + c * 8 + q * 2);
        const uint4* Jp = ((const uint4*)g_gib) + ((size_t)sai[m] * 128 + c * 8 + q * 2);
        iA[0] = Ip[0]; iA[1] = Ip[1];
        jA[0] = Jp[0]; jA[1] = Jp[1];
    };
    auto storeA = [&](int c) {
        uint32_t asb = rbase + (uint32_t)((c & 1) * 16384) + (uint32_t)(m * 128 + q * 32);
        #pragma unroll
        for (int t = 0; t < 2; t++) {
            uint4 r;
            r.x = mul2(iA[t].x, jA[t].x); r.y = mul2(iA[t].y, jA[t].y);
            r.z = mul2(iA[t].z, jA[t].z); r.w = mul2(iA[t].w, jA[t].w);
            STS128(r.x, r.y, r.z, r.w, SWZ(asb + t * 16));
        }
    };
    auto issueB = [&](int c) {
        uint32_t Bb = rbase + 32768u + (uint32_t)((c & 3) * 20480);
        const char* src = (const char*)(g_Bpack + c * 5120);
        #pragma unroll
        for (int t = 0; t < 3; t++) {
            int i = tid + t * 512;
            if (i < 1280) CPA16(Bb + (uint32_t)(i * 16), src + (size_t)i * 16);
        }
        CPC();
    };

    // ---- layer 1 pipeline: B 3 chunks ahead, 1 barrier/chunk ----
    issueB(0); issueB(1); issueB(2);
    loadA(0);
    storeA(0);
    for (int c = 0; c < NCHUNK; c++) {
        if (c + 1 < NCHUNK) loadA(c + 1);
        if (c < NCHUNK - 2) CPW2(); else if (c == NCHUNK - 2) CPW1(); else CPW0();
        __syncthreads();
        if (c + 3 < NCHUNK) issueB(c + 3);
        int s = c & 3;
        int nk = (c == NCHUNK - 1) ? 3 : 4;
        uint32_t Ab = rbase + (uint32_t)((c & 1) * 16384);
        uint32_t Bb = rbase + 32768u + (uint32_t)(s * 20480);
        if (nw < 3) mma_chunk40<2,true >(Ab, Bb, nk, mw * 32, nw * 40, lane, acc);
        else        mma_chunk40<2,false>(Ab, Bb, nk, mw * 32, nw * 40, lane, acc);
        if (c + 1 < NCHUNK) storeA(c + 1);
    }
    __syncthreads();   // all MMA reads done before H/W2 overwrite A/B regions

    // ---- W2^T cp.async ----
    {
        const char* src = (const char*)g_B2pack;
        #pragma unroll
        for (int t = 0; t < 8; t++) {
            int i = tid + t * 512;
            if (i < 3840) CPA16(W2b + (uint32_t)(i * 16), src + (size_t)i * 16);
        }
        CPC();
    }

    // ---- epilogue 1 pass A: raw acc -> bf16 H tile (all cols, zeros in tail) ----
    #pragma unroll
    for (int mt = 0; mt < 2; mt++)
        #pragma unroll
        for (int half = 0; half < 2; half++) {
            int r = mw * 32 + mt * 16 + (lane >> 2) + half * 8;
            #pragma unroll
            for (int nt = 0; nt < 5; nt++) {
                int cc = nw * 40 + nt * 8 + (lane & 3) * 2;
                uint32_t w; CVTB2(w, acc[mt][nt][half * 2], acc[mt][nt][half * 2 + 1]);
                int ch = cc >> 6;
                STS32(Hb + (uint32_t)(ch * 16384) + SWZ((uint32_t)(r * 128 + (cc & 63) * 2)), w);
            }
        }
    __syncthreads();

    // ---- epilogue 1 pass B: vectorized gather + base add + relu (in place) ----
    {
        int r = tid >> 2, qq = tid & 3;   // row r, cols qq*40 .. +39
        const uint4* Ar = ((const uint4*)(g_A + (size_t)smi[r] * 80)) + qq * 5;
        const uint4* Br = ((const uint4*)(g_B + (size_t)sai[r] * 80)) + qq * 5;
        const uint4* Tr = ((const uint4*)(g_T + (size_t)sti[r] * 80)) + qq * 5;
        uint4 a4[5], b4[5], t4[5];
        #pragma unroll
        for (int g = 0; g < 5; g++) { a4[g] = Ar[g]; b4[g] = Br[g]; t4[g] = Tr[g]; }
        #pragma unroll
        for (int g = 0; g < 5; g++) {
            int cc0 = qq * 40 + g * 8;
            uint32_t addr = Hb + (uint32_t)((cc0 >> 6) * 16384) +
                            SWZ((uint32_t)(r * 128 + (cc0 & 63) * 2));
            uint32_t h0, h1, h2, h3;
            LDS128(h0, h1, h2, h3, addr);
            uint32_t hw[4] = {h0, h1, h2, h3};
            const uint32_t* ap = (const uint32_t*)&a4[g];
            const uint32_t* bp = (const uint32_t*)&b4[g];
            const uint32_t* tp = (const uint32_t*)&t4[g];
            #pragma unroll
            for (int wv = 0; wv < 4; wv++) {
                float2 hv = unpack_bf2(hw[wv]);
                float2 av = unpack_bf2(ap[wv]);
                float2 bv = unpack_bf2(bp[wv]);
                float2 tv = unpack_bf2(tp[wv]);
                float x = fmaxf(hv.x + av.x + bv.x + tv.x, 0.f);
                float y = fmaxf(hv.y + av.y + bv.y + tv.y, 0.f);
                CVTB2(hw[wv], x, y);
            }
            STS128(hw[0], hw[1], hw[2], hw[3], addr);
        }
    }
    CPW0();
    __syncthreads();

    // ---- layer 2 ----
    #pragma unroll
    for (int i = 0; i < 2; i++)
        #pragma unroll
        for (int j = 0; j < 5; j++)
            #pragma unroll
            for (int k = 0; k < 4; k++) acc[i][j][k] = 0.f;
    #pragma unroll
    for (int ch = 0; ch < 3; ch++) {
        int nk = (ch == 2) ? 2 : 4;
        if (nw < 3) mma_chunk40<2,true >(Hb + ch * 16384, W2b + ch * 20480, nk, mw * 32, nw * 40, lane, acc);
        else        mma_chunk40<2,false>(Hb + ch * 16384, W2b + ch * 20480, nk, mw * 32, nw * 40, lane, acc);
    }

    // ---- epilogue 2: relu(+b2) . W3 -> reduce -> scores ----
    #pragma unroll
    for (int mt = 0; mt < 2; mt++)
        #pragma unroll
        for (int half = 0; half < 2; half++) {
            float part = 0.f;
            #pragma unroll
            for (int nt = 0; nt < 5; nt++) {
                int cc = nw * 40 + nt * 8 + (lane & 3) * 2;
                float h0 = fmaxf(acc[mt][nt][half * 2]     + s_b2[cc],     0.f);
                float h1 = fmaxf(acc[mt][nt][half * 2 + 1] + s_b2[cc + 1], 0.f);
                part += h0 * s_w3[cc] + h1 * s_w3[cc + 1];
            }
            part += __shfl_xor_sync(0xffffffffu, part, 1);
            part += __shfl_xor_sync(0xffffffffu, part, 2);
            if ((lane & 3) == 0) {
                int r = mw * 32 + mt * 16 + (lane >> 2) + half * 8;
                sred[r][nw] = part;
            }
        }
    __syncthreads();
    if (tid < 128) {
        int p = p0 + tid;
        if (p < P) {
            float s = sred[tid][0] + sred[tid][1] + sred[tid][2] + sred[tid][3]
                    + b3[0] + ms[smi[tid]] + ms[sai[tid]];
            g_scores[p] = s;
        }
    }
}

// ============================================================
__global__ __launch_bounds__(128) void k_softmax(const int* __restrict__ lengths,
                                                 float* __restrict__ out)
{
    int g = blockIdx.x;
    int tid = threadIdx.x;
    int len = lengths[g];
    int st = g_starts[g];
    __shared__ float sm[4], ss[4];

    float v = (tid < len) ? g_scores[st + tid] : -3.4e38f;
    float mx = v;
    #pragma unroll
    for (int o = 16; o > 0; o >>= 1) mx = fmaxf(mx, __shfl_xor_sync(0xffffffffu, mx, o));
    if ((tid & 31) == 0) sm[tid >> 5] = mx;
    __syncthreads();
    mx = fmaxf(fmaxf(sm[0], sm[1]), fmaxf(sm[2], sm[3]));
    mx = fmaxf(mx, 0.f);

    float e = (tid < len) ? expf(v - mx) : 0.f;
    float s = e;
    #pragma unroll
    for (int o = 16; o > 0; o >>= 1) s += __shfl_xor_sync(0xffffffffu, s, o);
    if ((tid & 31) == 0) ss[tid >> 5] = s;
    __syncthreads();

    float epse = expf(-mx);
    float denom = ss[0] + ss[1] + ss[2] + ss[3] + epse;
    float* row = out + (size_t)(g + 1) * GRIDW;
    if (tid < len) row[tid] = e / denom;
    if (tid == 0)  row[len] = epse / denom;
}

// ============================================================
extern "C" void kernel_launch(void* const* d_in, const int* in_sizes, int n_in,
                              void* d_out, int out_size)
{
    const float* gi   = (const float*)d_in[0];
    const float* ms   = (const float*)d_in[1];
    const float* de   = (const float*)d_in[2];
    const float* ge   = (const float*)d_in[3];
    const float* se   = (const float*)d_in[4];
    const float* W1   = (const float*)d_in[5];
    const float* b1   = (const float*)d_in[6];
    const float* W2   = (const float*)d_in[7];
    const float* b2   = (const float*)d_in[8];
    const float* W3   = (const float*)d_in[9];
    const float* b3   = (const float*)d_in[10];
    const int*   mi   = (const int*)d_in[11];
    const int*   ai   = (const int*)d_in[12];
    const int*   di   = (const int*)d_in[13];
    const int*   gidx = (const int*)d_in[14];
    const int*   si   = (const int*)d_in[15];
    const int*   lens = (const int*)d_in[16];
    const int*   segs = (const int*)d_in[17];
    const int*   offs = (const int*)d_in[18];
    float* out = (float*)d_out;

    const int P = in_sizes[11];
    const int M = in_sizes[16];
    const int NSPAN = in_sizes[0] / GDIM;   // 4096

    const int DS = 114688 + 1024;
    static int configured = 0;
    if (!configured) {
        cudaFuncSetAttribute(k_pre,   cudaFuncAttributeMaxDynamicSharedMemorySize, DS);
        cudaFuncSetAttribute(k_fused, cudaFuncAttributeMaxDynamicSharedMemorySize, DS);
        configured = 1;
    }

    long long prep_total = (long long)NSPAN * 512 + (2 * 16 + NCHUNK + 3) * 5120
                         + 216 * 80 + out_size + P;
    k_prep<<<(int)((prep_total + 255) / 256), 256>>>(gi, W1, W2, de, ge, se,
                                                     offs, segs, out,
                                                     NSPAN, P, out_size);

    k_pre<<<dim3(NSPAN / 64, 2), 512, DS>>>(b1);

    int NT = (P + 127) / 128;
    k_fused<<<NT, 512, DS>>>(b2, W3, b3, ms,
                             mi, ai, di, gidx, si, P);

    k_softmax<<<M, 128>>>(lens, out);
}

// round 13
// speedup vs baseline: 1.4502x; 1.0023x over previous
#include <cuda_runtime.h>
#include <cuda_bf16.h>
#include <cstdint>

#define HD 150
#define HP 160
#define GDIM 1000
#define GRIDW 129
#define NCHUNK 16

typedef unsigned long long ull;

// ---------------- helpers ----------------
__device__ __forceinline__ uint32_t smem_u32(const void* p){
    uint32_t a; asm("{ .reg .u64 t; cvta.to.shared.u64 t, %1; cvt.u32.u64 %0, t; }" : "=r"(a) : "l"(p));
    return a;
}
__device__ __forceinline__ uint32_t mul2(uint32_t a, uint32_t b){
    uint32_t r; asm("mul.bf16x2 %0,%1,%2;" : "=r"(r) : "r"(a), "r"(b)); return r;
}
#define CVTB2(res,a,b) asm("cvt.rn.satfinite.bf16x2.f32 %0, %1, %2;" : "=r"(res) : "f"(b), "f"(a))
#define STS128(r0,r1,r2,r3,addr) asm volatile("st.shared.v4.b32 [%0], {%1,%2,%3,%4};" :: "r"(addr), "r"(r0), "r"(r1), "r"(r2), "r"(r3) : "memory")
#define LDS128(r0,r1,r2,r3,addr) asm volatile("ld.shared.v4.b32 {%0,%1,%2,%3}, [%4];" : "=r"(r0),"=r"(r1),"=r"(r2),"=r"(r3) : "r"(addr))
#define STS32(addr,v) asm volatile("st.shared.b32 [%0], %1;" :: "r"(addr), "r"(v) : "memory")
#define SWZ(a) ((a) ^ (((a)>>3)&0x70))

__device__ __forceinline__ float2 unpack_bf2(uint32_t v){
    float2 r;
    r.x = __uint_as_float(v << 16);
    r.y = __uint_as_float(v & 0xffff0000u);
    return r;
}

#define CPA16(dst,src) asm volatile("cp.async.cg.shared.global [%0], [%1], 16;" :: "r"((uint32_t)(dst)), "l"(src) : "memory")
#define CPC() asm volatile("cp.async.commit_group;" ::: "memory")
#define CPW0() asm volatile("cp.async.wait_group 0;" ::: "memory")
#define CPW1() asm volatile("cp.async.wait_group 1;" ::: "memory")
#define CPW2() asm volatile("cp.async.wait_group 2;" ::: "memory")

#define LDSM4(r0,r1,r2,r3,addr) \
    asm volatile("ldmatrix.sync.aligned.m8n8.x4.shared.b16 {%0,%1,%2,%3}, [%4];" \
        : "=r"(r0),"=r"(r1),"=r"(r2),"=r"(r3) : "r"(addr))
#define LDSM2(r0,r1,addr) \
    asm volatile("ldmatrix.sync.aligned.m8n8.x2.shared.b16 {%0,%1}, [%2];" \
        : "=r"(r0),"=r"(r1) : "r"(addr))

#define MMA(d,a,b) \
    asm volatile("mma.sync.aligned.m16n8k16.row.col.f32.bf16.bf16.f32 " \
        "{%0,%1,%2,%3},{%4,%5,%6,%7},{%8,%9},{%0,%1,%2,%3};" \
        : "+f"((d)[0]),"+f"((d)[1]),"+f"((d)[2]),"+f"((d)[3]) \
        : "r"((a)[0]),"r"((a)[1]),"r"((a)[2]),"r"((a)[3]),"r"((b)[0]),"r"((b)[1]))

// ---------------- scratch ----------------
__device__ uint32_t g_gib[4096 * 512];          // gi as bf16x2, K padded to 1024
__device__ uint32_t g_ABpack[2 * 16 * 5120];    // W1a^T, W1b^T pre-swizzled chunks
__device__ uint32_t g_Bpack[NCHUNK * 5120];     // W1c^T chunks
__device__ uint32_t g_B2pack[3 * 5120];         // W2^T chunks
__device__ uint32_t g_A[4096 * 80];             // (gi@W1a + b1) bf16x2 (full 160 cols)
__device__ uint32_t g_B[4096 * 80];             // (gi@W1b) bf16x2
__device__ uint32_t g_T[216 * 80];              // combined phi tables bf16x2 (d*24+g*3+s)
__device__ float g_scores[132096];
__device__ int   g_starts[2048];

// ============================================================
// warp MMA consumer. TAIL=true: N40 (2xLDSM4 + LDSM2). TAIL=false: N32.
// ============================================================
template<int MT, bool TAIL>
__device__ __forceinline__ void mma_chunk40(uint32_t Ab, uint32_t Bb, int nk16,
                                            int mrow0, int nrow0, int lane,
                                            float (&acc)[MT][5][4])
{
    const int a_row = mrow0 + ((lane>>3)&1)*8 + (lane&7);
    const int a_cb  = (lane>>4)*16;
    const int b_row = nrow0 + ((lane>>4)&1)*8 + (lane&7);
    const int b_cb  = ((lane>>3)&1)*16;
    const int b2_row = nrow0 + 32 + (lane&7);
    const int b2_cb  = ((lane>>3)&1)*16;
    #pragma unroll
    for (int k16 = 0; k16 < nk16; k16++) {
        const int kb = k16 * 32;
        uint32_t a[MT][4];
        #pragma unroll
        for (int mt = 0; mt < MT; mt++) {
            uint32_t ad = Ab + SWZ((uint32_t)((a_row + mt*16)*128 + kb + a_cb));
            LDSM4(a[mt][0], a[mt][1], a[mt][2], a[mt][3], ad);
        }
        uint32_t b[5][2];
        #pragma unroll
        for (int g = 0; g < 2; g++) {
            uint32_t bd = Bb + SWZ((uint32_t)((b_row + g*16)*128 + kb + b_cb));
            uint32_t r0, r1, r2, r3;
            LDSM4(r0, r1, r2, r3, bd);
            b[2*g][0] = r0; b[2*g][1] = r1; b[2*g+1][0] = r2; b[2*g+1][1] = r3;
        }
        if constexpr (TAIL) {
            uint32_t bd = Bb + SWZ((uint32_t)(b2_row*128 + kb + b2_cb));
            LDSM2(b[4][0], b[4][1], bd);
        }
        #pragma unroll
        for (int mt = 0; mt < MT; mt++)
            #pragma unroll
            for (int nt = 0; nt < (TAIL ? 5 : 4); nt++)
                MMA(acc[mt][nt], a[mt], b[nt]);
    }
}

// ============================================================
// prep (fused: vectorized gi pack + weight packs + phi tables + fill + starts)
// ============================================================
__global__ void k_prep(const float* __restrict__ gi, const float* __restrict__ W1,
                       const float* __restrict__ W2,
                       const float* __restrict__ de, const float* __restrict__ ge,
                       const float* __restrict__ se,
                       const int* __restrict__ offs, const int* __restrict__ segs,
                       float* __restrict__ out, int NSPAN, int P, int out_total)
{
    long long idx = (long long)blockIdx.x * 256 + threadIdx.x;
    const long long NG  = (long long)NSPAN * 128;           // 4 words per thread
    const long long AB  = NG + 2 * 16 * 5120;
    const long long BP  = AB + NCHUNK * 5120;
    const long long B2E = BP + 3 * 5120;
    const long long TE  = B2E + 216 * 80;
    const long long FE  = TE + out_total;
    const long long SE  = FE + P;
    if (idx < NG) {
        int n = (int)(idx >> 7), w4 = (int)(idx & 127);
        int c0 = w4 * 8;                                    // first float of 8
        uint4 outw;
        if (c0 + 8 <= GDIM) {
            float4 f0 = *(const float4*)(gi + (size_t)n * GDIM + c0);
            float4 f1 = *(const float4*)(gi + (size_t)n * GDIM + c0 + 4);
            CVTB2(outw.x, f0.x, f0.y); CVTB2(outw.y, f0.z, f0.w);
            CVTB2(outw.z, f1.x, f1.y); CVTB2(outw.w, f1.z, f1.w);
        } else {
            float f[8];
            #pragma unroll
            for (int e = 0; e < 8; e++)
                f[e] = (c0 + e < GDIM) ? gi[(size_t)n * GDIM + c0 + e] : 0.f;
            CVTB2(outw.x, f[0], f[1]); CVTB2(outw.y, f[2], f[3]);
            CVTB2(outw.z, f[4], f[5]); CVTB2(outw.w, f[6], f[7]);
        }
        ((uint4*)g_gib)[idx] = outw;
    } else if (idx < AB) {
        int t = (int)(idx - NG);
        int sel = t / (16 * 5120); int rem = t - sel * 16 * 5120;
        int c = rem / 5120, r = rem % 5120;
        int n = r >> 5, kk = (r & 31) * 2;
        int kg = c * 64 + kk;
        float v0 = 0.f, v1 = 0.f;
        if (n < HD) {
            if (kg     < GDIM) v0 = W1[(size_t)(sel * GDIM + kg)     * HD + n];
            if (kg + 1 < GDIM) v1 = W1[(size_t)(sel * GDIM + kg + 1) * HD + n];
        }
        uint32_t w; CVTB2(w, v0, v1);
        uint32_t off = (uint32_t)(n * 128 + kk * 2);
        g_ABpack[(sel * 16 + c) * 5120 + (SWZ(off) >> 2)] = w;
    } else if (idx < BP) {
        int t = (int)(idx - AB);
        int c = t / 5120, r = t % 5120;
        int n = r >> 5, kk = (r & 31) * 2;
        int kg = c * 64 + kk;
        float v0 = 0.f, v1 = 0.f;
        if (n < HD) {
            if (kg     < GDIM) v0 = W1[(size_t)(2000 + kg) * HD + n];
            if (kg + 1 < GDIM) v1 = W1[(size_t)(2001 + kg) * HD + n];
        }
        uint32_t w; CVTB2(w, v0, v1);
        uint32_t off = (uint32_t)(n * 128 + kk * 2);
        g_Bpack[c * 5120 + (SWZ(off) >> 2)] = w;
    } else if (idx < B2E) {
        int t = (int)(idx - BP);
        int c = t / 5120, r = t % 5120;
        int n = r >> 5, kk = (r & 31) * 2;
        int kg = c * 64 + kk;
        float v0 = 0.f, v1 = 0.f;
        if (n < HD) {
            if (kg     < HD) v0 = W2[(size_t)kg       * HD + n];
            if (kg + 1 < HD) v1 = W2[(size_t)(kg + 1) * HD + n];
        }
        uint32_t w; CVTB2(w, v0, v1);
        uint32_t off = (uint32_t)(n * 128 + kk * 2);
        g_B2pack[c * 5120 + (SWZ(off) >> 2)] = w;
    } else if (idx < TE) {
        int t = (int)(idx - B2E);
        int r = t / 80, cc = (t % 80) * 2;
        int d = r / 24, rem = r % 24;
        int g = rem / 3, s = rem % 3;
        float v0 = 0.f, v1 = 0.f;
        if (cc < HD) {
            for (int k = 0; k < 20; k++) {
                float ed = de[d * 20 + k], eg = ge[g * 20 + k], es = se[s * 20 + k];
                v0 += ed * W1[(size_t)(3000 + k) * HD + cc]
                    + eg * W1[(size_t)(3020 + k) * HD + cc]
                    + es * W1[(size_t)(3040 + k) * HD + cc];
                if (cc + 1 < HD)
                    v1 += ed * W1[(size_t)(3000 + k) * HD + cc + 1]
                        + eg * W1[(size_t)(3020 + k) * HD + cc + 1]
                        + es * W1[(size_t)(3040 + k) * HD + cc + 1];
            }
        }
        uint32_t w; CVTB2(w, v0, v1);
        g_T[r * 80 + (cc >> 1)] = w;
    } else if (idx < FE) {
        long long i = idx - TE;
        out[i] = (i == 0) ? 1.0f : 1000.0f;
    } else if (idx < SE) {
        int p = (int)(idx - FE);
        if (offs[p] == 0) g_starts[segs[p]] = p;
    }
}

// ============================================================
// k_pre: g_A = (gi @ W1a) + b1, g_B = gi @ W1b  (bf16x2 output, full 160 cols)
// grid (NSPAN/64, 2, 2): x = M64 tile, y = sel, z = N-half (80 cols)
// 256 threads, warp grid 4x2: warp M16 x N40
// ============================================================
__global__ __launch_bounds__(256) void k_pre(const float* __restrict__ b1)
{
    extern __shared__ char dsm[];
    const int tid = threadIdx.x;
    const int lane = tid & 31;
    const int wid = tid >> 5;
    const int mw = wid & 3, nh = wid >> 2;     // mw 0..3, nh 0..1
    const int n0 = blockIdx.x * 64;
    const int sel = blockIdx.y;
    const int z = blockIdx.z;

    uint32_t rbase = (smem_u32(dsm) + 1023u) & ~1023u;
    // A slots 4x8KB [0,32768); B ring 4x10KB [32768,73728)
    const char* Bsrc = (const char*)(g_ABpack + sel * 16 * 5120) + (size_t)z * 10240;

    float acc[1][5][4];
    #pragma unroll
    for (int j = 0; j < 5; j++)
        #pragma unroll
        for (int k = 0; k < 4; k++) acc[0][j][k] = 0.f;

    auto issue = [&](int c) {
        int s = c & 3;
        uint32_t Ab = rbase + (uint32_t)(s * 8192);
        uint32_t Bb = rbase + 32768u + (uint32_t)(s * 10240);
        #pragma unroll
        for (int t = 0; t < 2; t++) {
            int i = tid + t * 256;   // 512 A vectors: 64 rows x 8 segs
            int row = i >> 3, seg = i & 7;
            const char* src = (const char*)g_gib + ((size_t)(n0 + row) * 2048 + c * 128 + seg * 16);
            CPA16(Ab + SWZ((uint32_t)(row * 128 + seg * 16)), src);
        }
        #pragma unroll
        for (int t = 0; t < 3; t++) {
            int j = tid + t * 256;
            if (j < 640) CPA16(Bb + (uint32_t)(j * 16), Bsrc + (size_t)c * 20480 + j * 16);
        }
        CPC();
    };

    const bool tail = !(z == 1 && nh == 1);    // dead cols 152..159 only there

    issue(0); issue(1); issue(2);
    for (int c = 0; c < 16; c++) {
        if (c <= 13) CPW2(); else if (c == 14) CPW1(); else CPW0();
        __syncthreads();
        if (c + 3 < 16) issue(c + 3);
        int s = c & 3;
        int nk = (c == 15) ? 3 : 4;
        uint32_t Ab = rbase + (uint32_t)(s * 8192);
        uint32_t Bb = rbase + 32768u + (uint32_t)(s * 10240);
        if (tail) mma_chunk40<1,true >(Ab, Bb, nk, mw * 16, nh * 40, lane, acc);
        else      mma_chunk40<1,false>(Ab, Bb, nk, mw * 16, nh * 40, lane, acc);
    }

    uint32_t* dst = sel ? g_B : g_A;
    #pragma unroll
    for (int half = 0; half < 2; half++) {
        int row = n0 + mw * 16 + (lane >> 2) + half * 8;
        #pragma unroll
        for (int nt = 0; nt < 5; nt++) {
            int cc = z * 80 + nh * 40 + nt * 8 + (lane & 3) * 2;
            float x = acc[0][nt][half * 2];
            float y = acc[0][nt][half * 2 + 1];
            if (!sel) {
                if (cc     < HD) x += b1[cc];
                if (cc + 1 < HD) y += b1[cc + 1];
            }
            uint32_t w; CVTB2(w, x, y);
            dst[(size_t)row * 80 + (cc >> 1)] = w;
        }
    }
}

// ============================================================
// fused pair kernel: layer1 HMMA + two-pass epilogue(+tables) + layer2 + score
// ============================================================
__global__ __launch_bounds__(512) void k_fused(
    const float* __restrict__ b2,
    const float* __restrict__ W3, const float* __restrict__ b3,
    const float* __restrict__ ms,
    const int* __restrict__ mi, const int* __restrict__ ai,
    const int* __restrict__ di, const int* __restrict__ gx, const int* __restrict__ si,
    int P)
{
    extern __shared__ char dsm[];
    __shared__ int smi[128], sai[128], sti[128];
    __shared__ __align__(16) float s_b2[HP], s_w3[HP];
    __shared__ float sred[128][4];

    const int tid = threadIdx.x;
    const int lane = tid & 31;
    const int wid = tid >> 5;
    const int mw = wid & 3, nw = wid >> 2;
    const int p0 = blockIdx.x * 128;

    uint32_t rbase = (smem_u32(dsm) + 1023u) & ~1023u;
    const uint32_t Hb  = rbase;
    const uint32_t W2b = rbase + 53248u;

    if (tid < 128) {
        int p = p0 + tid; if (p >= P) p = P - 1;
        smi[tid] = mi[p]; sai[tid] = ai[p];
        sti[tid] = di[p] * 24 + gx[p] * 3 + si[p];
    }
    if (tid >= 256 && tid < 256 + HP) {
        int h = tid - 256;
        s_b2[h] = (h < HD) ? b2[h] : 0.f;
        s_w3[h] = (h < HD) ? W3[h] : 0.f;
    }
    __syncthreads();

    float acc[2][5][4];
    #pragma unroll
    for (int i = 0; i < 2; i++)
        #pragma unroll
        for (int j = 0; j < 5; j++)
            #pragma unroll
            for (int k = 0; k < 4; k++) acc[i][j][k] = 0.f;

    const int m = tid >> 2, q = tid & 3;

    uint4 iA[2], jA[2];
    auto loadA = [&](int c) {
        const uint4* Ip = ((const uint4*)g_gib) + ((size_t)smi[m] * 128 + c * 8 + q * 2);
        const uint4* Jp = ((const uint4*)g_gib) + ((size_t)sai[m] * 128 + c * 8 + q * 2);
        iA[0] = Ip[0]; iA[1] = Ip[1];
        jA[0] = Jp[0]; jA[1] = Jp[1];
    };
    auto storeA = [&](int c) {
        uint32_t asb = rbase + (uint32_t)((c & 1) * 16384) + (uint32_t)(m * 128 + q * 32);
        #pragma unroll
        for (int t = 0; t < 2; t++) {
            uint4 r;
            r.x = mul2(iA[t].x, jA[t].x); r.y = mul2(iA[t].y, jA[t].y);
            r.z = mul2(iA[t].z, jA[t].z); r.w = mul2(iA[t].w, jA[t].w);
            STS128(r.x, r.y, r.z, r.w, SWZ(asb + t * 16));
        }
    };
    auto issueB = [&](int c) {
        uint32_t Bb = rbase + 32768u + (uint32_t)((c & 3) * 20480);
        const char* src = (const char*)(g_Bpack + c * 5120);
        #pragma unroll
        for (int t = 0; t < 3; t++) {
            int i = tid + t * 512;
            if (i < 1280) CPA16(Bb + (uint32_t)(i * 16), src + (size_t)i * 16);
        }
        CPC();
    };

    // ---- layer 1 pipeline: B 3 chunks ahead, 1 barrier/chunk ----
    issueB(0); issueB(1); issueB(2);
    loadA(0);
    storeA(0);
    for (int c = 0; c < NCHUNK; c++) {
        if (c + 1 < NCHUNK) loadA(c + 1);
        if (c < NCHUNK - 2) CPW2(); else if (c == NCHUNK - 2) CPW1(); else CPW0();
        __syncthreads();
        if (c + 3 < NCHUNK) issueB(c + 3);
        int s = c & 3;
        int nk = (c == NCHUNK - 1) ? 3 : 4;
        uint32_t Ab = rbase + (uint32_t)((c & 1) * 16384);
        uint32_t Bb = rbase + 32768u + (uint32_t)(s * 20480);
        if (nw < 3) mma_chunk40<2,true >(Ab, Bb, nk, mw * 32, nw * 40, lane, acc);
        else        mma_chunk40<2,false>(Ab, Bb, nk, mw * 32, nw * 40, lane, acc);
        if (c + 1 < NCHUNK) storeA(c + 1);
    }
    __syncthreads();   // all MMA reads done before H/W2 overwrite A/B regions

    // ---- W2^T cp.async ----
    {
        const char* src = (const char*)g_B2pack;
        #pragma unroll
        for (int t = 0; t < 8; t++) {
            int i = tid + t * 512;
            if (i < 3840) CPA16(W2b + (uint32_t)(i * 16), src + (size_t)i * 16);
        }
        CPC();
    }

    // ---- epilogue 1 pass A: raw acc -> bf16 H tile (all cols, zeros in tail) ----
    #pragma unroll
    for (int mt = 0; mt < 2; mt++)
        #pragma unroll
        for (int half = 0; half < 2; half++) {
            int r = mw * 32 + mt * 16 + (lane >> 2) + half * 8;
            #pragma unroll
            for (int nt = 0; nt < 5; nt++) {
                int cc = nw * 40 + nt * 8 + (lane & 3) * 2;
                uint32_t w; CVTB2(w, acc[mt][nt][half * 2], acc[mt][nt][half * 2 + 1]);
                int ch = cc >> 6;
                STS32(Hb + (uint32_t)(ch * 16384) + SWZ((uint32_t)(r * 128 + (cc & 63) * 2)), w);
            }
        }
    __syncthreads();

    // ---- epilogue 1 pass B: vectorized gather + base add + relu (in place) ----
    {
        int r = tid >> 2, qq = tid & 3;   // row r, cols qq*40 .. +39
        const uint4* Ar = ((const uint4*)(g_A + (size_t)smi[r] * 80)) + qq * 5;
        const uint4* Br = ((const uint4*)(g_B + (size_t)sai[r] * 80)) + qq * 5;
        const uint4* Tr = ((const uint4*)(g_T + (size_t)sti[r] * 80)) + qq * 5;
        uint4 a4[5], b4[5], t4[5];
        #pragma unroll
        for (int g = 0; g < 5; g++) { a4[g] = Ar[g]; b4[g] = Br[g]; t4[g] = Tr[g]; }
        #pragma unroll
        for (int g = 0; g < 5; g++) {
            int cc0 = qq * 40 + g * 8;
            uint32_t addr = Hb + (uint32_t)((cc0 >> 6) * 16384) +
                            SWZ((uint32_t)(r * 128 + (cc0 & 63) * 2));
            uint32_t h0, h1, h2, h3;
            LDS128(h0, h1, h2, h3, addr);
            uint32_t hw[4] = {h0, h1, h2, h3};
            const uint32_t* ap = (const uint32_t*)&a4[g];
            const uint32_t* bp = (const uint32_t*)&b4[g];
            const uint32_t* tp = (const uint32_t*)&t4[g];
            #pragma unroll
            for (int wv = 0; wv < 4; wv++) {
                float2 hv = unpack_bf2(hw[wv]);
                float2 av = unpack_bf2(ap[wv]);
                float2 bv = unpack_bf2(bp[wv]);
                float2 tv = unpack_bf2(tp[wv]);
                float x = fmaxf(hv.x + av.x + bv.x + tv.x, 0.f);
                float y = fmaxf(hv.y + av.y + bv.y + tv.y, 0.f);
                CVTB2(hw[wv], x, y);
            }
            STS128(hw[0], hw[1], hw[2], hw[3], addr);
        }
    }
    CPW0();
    __syncthreads();

    // ---- layer 2 ----
    #pragma unroll
    for (int i = 0; i < 2; i++)
        #pragma unroll
        for (int j = 0; j < 5; j++)
            #pragma unroll
            for (int k = 0; k < 4; k++) acc[i][j][k] = 0.f;
    #pragma unroll
    for (int ch = 0; ch < 3; ch++) {
        int nk = (ch == 2) ? 2 : 4;
        if (nw < 3) mma_chunk40<2,true >(Hb + ch * 16384, W2b + ch * 20480, nk, mw * 32, nw * 40, lane, acc);
        else        mma_chunk40<2,false>(Hb + ch * 16384, W2b + ch * 20480, nk, mw * 32, nw * 40, lane, acc);
    }

    // ---- epilogue 2: relu(+b2) . W3 -> reduce -> scores ----
    #pragma unroll
    for (int mt = 0; mt < 2; mt++)
        #pragma unroll
        for (int half = 0; half < 2; half++) {
            float part = 0.f;
            #pragma unroll
            for (int nt = 0; nt < 5; nt++) {
                int cc = nw * 40 + nt * 8 + (lane & 3) * 2;
                float h0 = fmaxf(acc[mt][nt][half * 2]     + s_b2[cc],     0.f);
                float h1 = fmaxf(acc[mt][nt][half * 2 + 1] + s_b2[cc + 1], 0.f);
                part += h0 * s_w3[cc] + h1 * s_w3[cc + 1];
            }
            part += __shfl_xor_sync(0xffffffffu, part, 1);
            part += __shfl_xor_sync(0xffffffffu, part, 2);
            if ((lane & 3) == 0) {
                int r = mw * 32 + mt * 16 + (lane >> 2) + half * 8;
                sred[r][nw] = part;
            }
        }
    __syncthreads();
    if (tid < 128) {
        int p = p0 + tid;
        if (p < P) {
            float s = sred[tid][0] + sred[tid][1] + sred[tid][2] + sred[tid][3]
                    + b3[0] + ms[smi[tid]] + ms[sai[tid]];
            g_scores[p] = s;
        }
    }
}

// ============================================================
__global__ __launch_bounds__(128) void k_softmax(const int* __restrict__ lengths,
                                                 float* __restrict__ out)
{
    int g = blockIdx.x;
    int tid = threadIdx.x;
    int len = lengths[g];
    int st = g_starts[g];
    __shared__ float sm[4], ss[4];

    float v = (tid < len) ? g_scores[st + tid] : -3.4e38f;
    float mx = v;
    #pragma unroll
    for (int o = 16; o > 0; o >>= 1) mx = fmaxf(mx, __shfl_xor_sync(0xffffffffu, mx, o));
    if ((tid & 31) == 0) sm[tid >> 5] = mx;
    __syncthreads();
    mx = fmaxf(fmaxf(sm[0], sm[1]), fmaxf(sm[2], sm[3]));
    mx = fmaxf(mx, 0.f);

    float e = (tid < len) ? expf(v - mx) : 0.f;
    float s = e;
    #pragma unroll
    for (int o = 16; o > 0; o >>= 1) s += __shfl_xor_sync(0xffffffffu, s, o);
    if ((tid & 31) == 0) ss[tid >> 5] = s;
    __syncthreads();

    float epse = expf(-mx);
    float denom = ss[0] + ss[1] + ss[2] + ss[3] + epse;
    float* row = out + (size_t)(g + 1) * GRIDW;
    if (tid < len) row[tid] = e / denom;
    if (tid == 0)  row[len] = epse / denom;
}

// ============================================================
extern "C" void kernel_launch(void* const* d_in, const int* in_sizes, int n_in,
                              void* d_out, int out_size)
{
    const float* gi   = (const float*)d_in[0];
    const float* ms   = (const float*)d_in[1];
    const float* de   = (const float*)d_in[2];
    const float* ge   = (const float*)d_in[3];
    const float* se   = (const float*)d_in[4];
    const float* W1   = (const float*)d_in[5];
    const float* b1   = (const float*)d_in[6];
    const float* W2   = (const float*)d_in[7];
    const float* b2   = (const float*)d_in[8];
    const float* W3   = (const float*)d_in[9];
    const float* b3   = (const float*)d_in[10];
    const int*   mi   = (const int*)d_in[11];
    const int*   ai   = (const int*)d_in[12];
    const int*   di   = (const int*)d_in[13];
    const int*   gidx = (const int*)d_in[14];
    const int*   si   = (const int*)d_in[15];
    const int*   lens = (const int*)d_in[16];
    const int*   segs = (const int*)d_in[17];
    const int*   offs = (const int*)d_in[18];
    float* out = (float*)d_out;

    const int P = in_sizes[11];
    const int M = in_sizes[16];
    const int NSPAN = in_sizes[0] / GDIM;   // 4096

    const int DS_PRE   = 73728 + 1024;
    const int DS_FUSED = 114688 + 1024;
    static int configured = 0;
    if (!configured) {
        cudaFuncSetAttribute(k_pre,   cudaFuncAttributeMaxDynamicSharedMemorySize, DS_PRE);
        cudaFuncSetAttribute(k_fused, cudaFuncAttributeMaxDynamicSharedMemorySize, DS_FUSED);
        configured = 1;
    }

    long long prep_total = (long long)NSPAN * 128 + (2 * 16 + NCHUNK + 3) * 5120
                         + 216 * 80 + out_size + P;
    k_prep<<<(int)((prep_total + 255) / 256), 256>>>(gi, W1, W2, de, ge, se,
                                                     offs, segs, out,
                                                     NSPAN, P, out_size);

    k_pre<<<dim3(NSPAN / 64, 2, 2), 256, DS_PRE>>>(b1);

    int NT = (P + 127) / 128;
    k_fused<<<NT, 512, DS_FUSED>>>(b2, W3, b3, ms,
                                   mi, ai, di, gidx, si, P);

    k_softmax<<<M, 128>>>(lens, out);
}

// round 14
// speedup vs baseline: 1.4760x; 1.0178x over previous
#include <cuda_runtime.h>
#include <cuda_bf16.h>
#include <cstdint>

#define HD 150
#define HP 160
#define GDIM 1000
#define GRIDW 129
#define NCHUNK 16
#define CHW 4864          // words per 152-row B chunk
#define CHB 19456         // bytes per 152-row B chunk (1024-aligned)

typedef unsigned long long ull;

// ---------------- helpers ----------------
__device__ __forceinline__ uint32_t smem_u32(const void* p){
    uint32_t a; asm("{ .reg .u64 t; cvta.to.shared.u64 t, %1; cvt.u32.u64 %0, t; }" : "=r"(a) : "l"(p));
    return a;
}
__device__ __forceinline__ uint32_t mul2(uint32_t a, uint32_t b){
    uint32_t r; asm("mul.bf16x2 %0,%1,%2;" : "=r"(r) : "r"(a), "r"(b)); return r;
}
#define CVTB2(res,a,b) asm("cvt.rn.satfinite.bf16x2.f32 %0, %1, %2;" : "=r"(res) : "f"(b), "f"(a))
#define STS128(r0,r1,r2,r3,addr) asm volatile("st.shared.v4.b32 [%0], {%1,%2,%3,%4};" :: "r"(addr), "r"(r0), "r"(r1), "r"(r2), "r"(r3) : "memory")
#define LDS128(r0,r1,r2,r3,addr) asm volatile("ld.shared.v4.b32 {%0,%1,%2,%3}, [%4];" : "=r"(r0),"=r"(r1),"=r"(r2),"=r"(r3) : "r"(addr))
#define STS32(addr,v) asm volatile("st.shared.b32 [%0], %1;" :: "r"(addr), "r"(v) : "memory")
#define SWZ(a) ((a) ^ (((a)>>3)&0x70))

__device__ __forceinline__ float2 unpack_bf2(uint32_t v){
    float2 r;
    r.x = __uint_as_float(v << 16);
    r.y = __uint_as_float(v & 0xffff0000u);
    return r;
}

#define CPA16(dst,src) asm volatile("cp.async.cg.shared.global [%0], [%1], 16;" :: "r"((uint32_t)(dst)), "l"(src) : "memory")
#define CPC() asm volatile("cp.async.commit_group;" ::: "memory")
#define CPW0() asm volatile("cp.async.wait_group 0;" ::: "memory")
#define CPW1() asm volatile("cp.async.wait_group 1;" ::: "memory")
#define CPW2() asm volatile("cp.async.wait_group 2;" ::: "memory")

#define LDSM4(r0,r1,r2,r3,addr) \
    asm volatile("ldmatrix.sync.aligned.m8n8.x4.shared.b16 {%0,%1,%2,%3}, [%4];" \
        : "=r"(r0),"=r"(r1),"=r"(r2),"=r"(r3) : "r"(addr))
#define LDSM2(r0,r1,addr) \
    asm volatile("ldmatrix.sync.aligned.m8n8.x2.shared.b16 {%0,%1}, [%2];" \
        : "=r"(r0),"=r"(r1) : "r"(addr))

#define MMA(d,a,b) \
    asm volatile("mma.sync.aligned.m16n8k16.row.col.f32.bf16.bf16.f32 " \
        "{%0,%1,%2,%3},{%4,%5,%6,%7},{%8,%9},{%0,%1,%2,%3};" \
        : "+f"((d)[0]),"+f"((d)[1]),"+f"((d)[2]),"+f"((d)[3]) \
        : "r"((a)[0]),"r"((a)[1]),"r"((a)[2]),"r"((a)[3]),"r"((b)[0]),"r"((b)[1]))

// ---------------- scratch ----------------
__device__ uint32_t g_gib[4096 * 512];          // gi as bf16x2, K padded to 1024
__device__ uint32_t g_ABpack[2 * 16 * CHW];     // W1a^T, W1b^T pre-swizzled (152-row chunks)
__device__ uint32_t g_Bpack[NCHUNK * CHW];      // W1c^T chunks
__device__ uint32_t g_B2pack[3 * CHW];          // W2^T chunks
__device__ uint32_t g_A[4096 * 80];             // (gi@W1a + b1) bf16x2 (full 160 cols)
__device__ uint32_t g_B[4096 * 80];             // (gi@W1b) bf16x2
__device__ uint32_t g_T[216 * 80];              // combined phi tables bf16x2 (d*24+g*3+s)
__device__ float g_scores[132096];
__device__ int   g_starts[2048];

// ============================================================
// warp MMA consumer. TAIL=true: N40 (2xLDSM4 + LDSM2). TAIL=false: N32.
// ============================================================
template<int MT, bool TAIL>
__device__ __forceinline__ void mma_chunk40(uint32_t Ab, uint32_t Bb, int nk16,
                                            int mrow0, int nrow0, int lane,
                                            float (&acc)[MT][5][4])
{
    const int a_row = mrow0 + ((lane>>3)&1)*8 + (lane&7);
    const int a_cb  = (lane>>4)*16;
    const int b_row = nrow0 + ((lane>>4)&1)*8 + (lane&7);
    const int b_cb  = ((lane>>3)&1)*16;
    const int b2_row = nrow0 + 32 + (lane&7);
    const int b2_cb  = ((lane>>3)&1)*16;
    #pragma unroll
    for (int k16 = 0; k16 < nk16; k16++) {
        const int kb = k16 * 32;
        uint32_t a[MT][4];
        #pragma unroll
        for (int mt = 0; mt < MT; mt++) {
            uint32_t ad = Ab + SWZ((uint32_t)((a_row + mt*16)*128 + kb + a_cb));
            LDSM4(a[mt][0], a[mt][1], a[mt][2], a[mt][3], ad);
        }
        uint32_t b[5][2];
        #pragma unroll
        for (int g = 0; g < 2; g++) {
            uint32_t bd = Bb + SWZ((uint32_t)((b_row + g*16)*128 + kb + b_cb));
            uint32_t r0, r1, r2, r3;
            LDSM4(r0, r1, r2, r3, bd);
            b[2*g][0] = r0; b[2*g][1] = r1; b[2*g+1][0] = r2; b[2*g+1][1] = r3;
        }
        if constexpr (TAIL) {
            uint32_t bd = Bb + SWZ((uint32_t)(b2_row*128 + kb + b2_cb));
            LDSM2(b[4][0], b[4][1], bd);
        }
        #pragma unroll
        for (int mt = 0; mt < MT; mt++)
            #pragma unroll
            for (int nt = 0; nt < (TAIL ? 5 : 4); nt++)
                MMA(acc[mt][nt], a[mt], b[nt]);
    }
}

// ============================================================
// prep (fused: vectorized gi pack + 152-row weight packs + phi tables + fill + starts)
// ============================================================
__global__ void k_prep(const float* __restrict__ gi, const float* __restrict__ W1,
                       const float* __restrict__ W2,
                       const float* __restrict__ de, const float* __restrict__ ge,
                       const float* __restrict__ se,
                       const int* __restrict__ offs, const int* __restrict__ segs,
                       float* __restrict__ out, int NSPAN, int P, int out_total)
{
    long long idx = (long long)blockIdx.x * 256 + threadIdx.x;
    const long long NG  = (long long)NSPAN * 128;           // 8 floats per thread
    const long long AB  = NG + 2 * 16 * CHW;
    const long long BP  = AB + NCHUNK * CHW;
    const long long B2E = BP + 3 * CHW;
    const long long TE  = B2E + 216 * 80;
    const long long FE  = TE + out_total;
    const long long SE  = FE + P;
    if (idx < NG) {
        int n = (int)(idx >> 7), w4 = (int)(idx & 127);
        int c0 = w4 * 8;
        uint4 outw;
        if (c0 + 8 <= GDIM) {
            float4 f0 = *(const float4*)(gi + (size_t)n * GDIM + c0);
            float4 f1 = *(const float4*)(gi + (size_t)n * GDIM + c0 + 4);
            CVTB2(outw.x, f0.x, f0.y); CVTB2(outw.y, f0.z, f0.w);
            CVTB2(outw.z, f1.x, f1.y); CVTB2(outw.w, f1.z, f1.w);
        } else {
            float f[8];
            #pragma unroll
            for (int e = 0; e < 8; e++)
                f[e] = (c0 + e < GDIM) ? gi[(size_t)n * GDIM + c0 + e] : 0.f;
            CVTB2(outw.x, f[0], f[1]); CVTB2(outw.y, f[2], f[3]);
            CVTB2(outw.z, f[4], f[5]); CVTB2(outw.w, f[6], f[7]);
        }
        ((uint4*)g_gib)[idx] = outw;
    } else if (idx < AB) {
        int t = (int)(idx - NG);
        int sel = t / (16 * CHW); int rem = t - sel * 16 * CHW;
        int c = rem / CHW, r = rem % CHW;
        int n = r >> 5, kk = (r & 31) * 2;
        int kg = c * 64 + kk;
        float v0 = 0.f, v1 = 0.f;
        if (n < HD) {
            if (kg     < GDIM) v0 = W1[(size_t)(sel * GDIM + kg)     * HD + n];
            if (kg + 1 < GDIM) v1 = W1[(size_t)(sel * GDIM + kg + 1) * HD + n];
        }
        uint32_t w; CVTB2(w, v0, v1);
        uint32_t off = (uint32_t)(n * 128 + kk * 2);
        g_ABpack[(sel * 16 + c) * CHW + (SWZ(off) >> 2)] = w;
    } else if (idx < BP) {
        int t = (int)(idx - AB);
        int c = t / CHW, r = t % CHW;
        int n = r >> 5, kk = (r & 31) * 2;
        int kg = c * 64 + kk;
        float v0 = 0.f, v1 = 0.f;
        if (n < HD) {
            if (kg     < GDIM) v0 = W1[(size_t)(2000 + kg) * HD + n];
            if (kg + 1 < GDIM) v1 = W1[(size_t)(2001 + kg) * HD + n];
        }
        uint32_t w; CVTB2(w, v0, v1);
        uint32_t off = (uint32_t)(n * 128 + kk * 2);
        g_Bpack[c * CHW + (SWZ(off) >> 2)] = w;
    } else if (idx < B2E) {
        int t = (int)(idx - BP);
        int c = t / CHW, r = t % CHW;
        int n = r >> 5, kk = (r & 31) * 2;
        int kg = c * 64 + kk;
        float v0 = 0.f, v1 = 0.f;
        if (n < HD) {
            if (kg     < HD) v0 = W2[(size_t)kg       * HD + n];
            if (kg + 1 < HD) v1 = W2[(size_t)(kg + 1) * HD + n];
        }
        uint32_t w; CVTB2(w, v0, v1);
        uint32_t off = (uint32_t)(n * 128 + kk * 2);
        g_B2pack[c * CHW + (SWZ(off) >> 2)] = w;
    } else if (idx < TE) {
        int t = (int)(idx - B2E);
        int r = t / 80, cc = (t % 80) * 2;
        int d = r / 24, rem = r % 24;
        int g = rem / 3, s = rem % 3;
        float v0 = 0.f, v1 = 0.f;
        if (cc < HD) {
            for (int k = 0; k < 20; k++) {
                float ed = de[d * 20 + k], eg = ge[g * 20 + k], es = se[s * 20 + k];
                v0 += ed * W1[(size_t)(3000 + k) * HD + cc]
                    + eg * W1[(size_t)(3020 + k) * HD + cc]
                    + es * W1[(size_t)(3040 + k) * HD + cc];
                if (cc + 1 < HD)
                    v1 += ed * W1[(size_t)(3000 + k) * HD + cc + 1]
                        + eg * W1[(size_t)(3020 + k) * HD + cc + 1]
                        + es * W1[(size_t)(3040 + k) * HD + cc + 1];
            }
        }
        uint32_t w; CVTB2(w, v0, v1);
        g_T[r * 80 + (cc >> 1)] = w;
    } else if (idx < FE) {
        long long i = idx - TE;
        out[i] = (i == 0) ? 1.0f : 1000.0f;
    } else if (idx < SE) {
        int p = (int)(idx - FE);
        if (offs[p] == 0) g_starts[segs[p]] = p;
    }
}

// ============================================================
// k_pre: g_A = (gi @ W1a) + b1, g_B = gi @ W1b  (bf16x2 output, full 160 cols)
// grid (NSPAN/64, 2, 2): x = M64 tile, y = sel, z = N-half
// z=0: B rows 0..79 (10240B); z=1: B rows 80..151 (9216B)
// ============================================================
__global__ __launch_bounds__(256) void k_pre(const float* __restrict__ b1)
{
    extern __shared__ char dsm[];
    const int tid = threadIdx.x;
    const int lane = tid & 31;
    const int wid = tid >> 5;
    const int mw = wid & 3, nh = wid >> 2;
    const int n0 = blockIdx.x * 64;
    const int sel = blockIdx.y;
    const int z = blockIdx.z;

    uint32_t rbase = (smem_u32(dsm) + 1023u) & ~1023u;
    const char* Bsrc = (const char*)(g_ABpack + sel * 16 * CHW) + (z ? 10240 : 0);
    const int nB = z ? 576 : 640;

    float acc[1][5][4];
    #pragma unroll
    for (int j = 0; j < 5; j++)
        #pragma unroll
        for (int k = 0; k < 4; k++) acc[0][j][k] = 0.f;

    auto issue = [&](int c) {
        int s = c & 3;
        uint32_t Ab = rbase + (uint32_t)(s * 8192);
        uint32_t Bb = rbase + 32768u + (uint32_t)(s * 10240);
        #pragma unroll
        for (int t = 0; t < 2; t++) {
            int i = tid + t * 256;
            int row = i >> 3, seg = i & 7;
            const char* src = (const char*)g_gib + ((size_t)(n0 + row) * 2048 + c * 128 + seg * 16);
            CPA16(Ab + SWZ((uint32_t)(row * 128 + seg * 16)), src);
        }
        #pragma unroll
        for (int t = 0; t < 3; t++) {
            int j = tid + t * 256;
            if (j < nB) CPA16(Bb + (uint32_t)(j * 16), Bsrc + (size_t)c * CHB + j * 16);
        }
        CPC();
    };

    const bool tail = !(z == 1 && nh == 1);

    issue(0); issue(1); issue(2);
    for (int c = 0; c < 16; c++) {
        if (c <= 13) CPW2(); else if (c == 14) CPW1(); else CPW0();
        __syncthreads();
        if (c + 3 < 16) issue(c + 3);
        int s = c & 3;
        int nk = (c == 15) ? 3 : 4;
        uint32_t Ab = rbase + (uint32_t)(s * 8192);
        uint32_t Bb = rbase + 32768u + (uint32_t)(s * 10240);
        if (tail) mma_chunk40<1,true >(Ab, Bb, nk, mw * 16, nh * 40, lane, acc);
        else      mma_chunk40<1,false>(Ab, Bb, nk, mw * 16, nh * 40, lane, acc);
    }

    uint32_t* dst = sel ? g_B : g_A;
    #pragma unroll
    for (int half = 0; half < 2; half++) {
        int row = n0 + mw * 16 + (lane >> 2) + half * 8;
        #pragma unroll
        for (int nt = 0; nt < 5; nt++) {
            int cc = z * 80 + nh * 40 + nt * 8 + (lane & 3) * 2;
            float x = acc[0][nt][half * 2];
            float y = acc[0][nt][half * 2 + 1];
            if (!sel) {
                if (cc     < HD) x += b1[cc];
                if (cc + 1 < HD) y += b1[cc + 1];
            }
            uint32_t w; CVTB2(w, x, y);
            dst[(size_t)row * 80 + (cc >> 1)] = w;
        }
    }
}

// ============================================================
// fused pair kernel: layer1 HMMA + two-pass epilogue(+tables) + layer2 + score
// B ring 4 x 19456B; W2 3 x 19456B
// ============================================================
__global__ __launch_bounds__(512) void k_fused(
    const float* __restrict__ b2,
    const float* __restrict__ W3, const float* __restrict__ b3,
    const float* __restrict__ ms,
    const int* __restrict__ mi, const int* __restrict__ ai,
    const int* __restrict__ di, const int* __restrict__ gx, const int* __restrict__ si,
    int P)
{
    extern __shared__ char dsm[];
    __shared__ int smi[128], sai[128], sti[128];
    __shared__ __align__(16) float s_b2[HP], s_w3[HP];
    __shared__ float sred[128][4];

    const int tid = threadIdx.x;
    const int lane = tid & 31;
    const int wid = tid >> 5;
    const int mw = wid & 3, nw = wid >> 2;
    const int p0 = blockIdx.x * 128;

    uint32_t rbase = (smem_u32(dsm) + 1023u) & ~1023u;
    const uint32_t Hb  = rbase;                 // 3 x 16KB = 49152
    const uint32_t W2b = rbase + 49152u;        // 3 x 19456 = 58368, end 107520

    if (tid < 128) {
        int p = p0 + tid; if (p >= P) p = P - 1;
        smi[tid] = mi[p]; sai[tid] = ai[p];
        sti[tid] = di[p] * 24 + gx[p] * 3 + si[p];
    }
    if (tid >= 256 && tid < 256 + HP) {
        int h = tid - 256;
        s_b2[h] = (h < HD) ? b2[h] : 0.f;
        s_w3[h] = (h < HD) ? W3[h] : 0.f;
    }
    __syncthreads();

    float acc[2][5][4];
    #pragma unroll
    for (int i = 0; i < 2; i++)
        #pragma unroll
        for (int j = 0; j < 5; j++)
            #pragma unroll
            for (int k = 0; k < 4; k++) acc[i][j][k] = 0.f;

    const int m = tid >> 2, q = tid & 3;

    uint4 iA[2], jA[2];
    auto loadA = [&](int c) {
        const uint4* Ip = ((const uint4*)g_gib) + ((size_t)smi[m] * 128 + c * 8 + q * 2);
        const uint4* Jp = ((const uint4*)g_gib) + ((size_t)sai[m] * 128 + c * 8 + q * 2);
        iA[0] = Ip[0]; iA[1] = Ip[1];
        jA[0] = Jp[0]; jA[1] = Jp[1];
    };
    auto storeA = [&](int c) {
        uint32_t asb = rbase + (uint32_t)((c & 1) * 16384) + (uint32_t)(m * 128 + q * 32);
        #pragma unroll
        for (int t = 0; t < 2; t++) {
            uint4 r;
            r.x = mul2(iA[t].x, jA[t].x); r.y = mul2(iA[t].y, jA[t].y);
            r.z = mul2(iA[t].z, jA[t].z); r.w = mul2(iA[t].w, jA[t].w);
            STS128(r.x, r.y, r.z, r.w, SWZ(asb + t * 16));
        }
    };
    auto issueB = [&](int c) {
        uint32_t Bb = rbase + 32768u + (uint32_t)((c & 3) * CHB);
        const char* src = (const char*)(g_Bpack + c * CHW);
        #pragma unroll
        for (int t = 0; t < 3; t++) {
            int i = tid + t * 512;
            if (i < 1216) CPA16(Bb + (uint32_t)(i * 16), src + (size_t)i * 16);
        }
        CPC();
    };

    // ---- layer 1 pipeline: B 3 chunks ahead, 1 barrier/chunk ----
    issueB(0); issueB(1); issueB(2);
    loadA(0);
    storeA(0);
    for (int c = 0; c < NCHUNK; c++) {
        if (c + 1 < NCHUNK) loadA(c + 1);
        if (c < NCHUNK - 2) CPW2(); else if (c == NCHUNK - 2) CPW1(); else CPW0();
        __syncthreads();
        if (c + 3 < NCHUNK) issueB(c + 3);
        int s = c & 3;
        int nk = (c == NCHUNK - 1) ? 3 : 4;
        uint32_t Ab = rbase + (uint32_t)((c & 1) * 16384);
        uint32_t Bb = rbase + 32768u + (uint32_t)(s * CHB);
        if (nw < 3) mma_chunk40<2,true >(Ab, Bb, nk, mw * 32, nw * 40, lane, acc);
        else        mma_chunk40<2,false>(Ab, Bb, nk, mw * 32, nw * 40, lane, acc);
        if (c + 1 < NCHUNK) storeA(c + 1);
    }
    __syncthreads();   // all MMA reads done before H/W2 overwrite A/B regions

    // ---- W2^T cp.async ----
    {
        const char* src = (const char*)g_B2pack;
        #pragma unroll
        for (int t = 0; t < 8; t++) {
            int i = tid + t * 512;
            if (i < 3648) CPA16(W2b + (uint32_t)(i * 16), src + (size_t)i * 16);
        }
        CPC();
    }

    // ---- epilogue 1 pass A: raw acc -> bf16 H tile (all cols, zeros in tail) ----
    #pragma unroll
    for (int mt = 0; mt < 2; mt++)
        #pragma unroll
        for (int half = 0; half < 2; half++) {
            int r = mw * 32 + mt * 16 + (lane >> 2) + half * 8;
            #pragma unroll
            for (int nt = 0; nt < 5; nt++) {
                int cc = nw * 40 + nt * 8 + (lane & 3) * 2;
                uint32_t w; CVTB2(w, acc[mt][nt][half * 2], acc[mt][nt][half * 2 + 1]);
                int ch = cc >> 6;
                STS32(Hb + (uint32_t)(ch * 16384) + SWZ((uint32_t)(r * 128 + (cc & 63) * 2)), w);
            }
        }
    __syncthreads();

    // ---- epilogue 1 pass B: vectorized gather + base add + relu (in place) ----
    {
        int r = tid >> 2, qq = tid & 3;
        const uint4* Ar = ((const uint4*)(g_A + (size_t)smi[r] * 80)) + qq * 5;
        const uint4* Br = ((const uint4*)(g_B + (size_t)sai[r] * 80)) + qq * 5;
        const uint4* Tr = ((const uint4*)(g_T + (size_t)sti[r] * 80)) + qq * 5;
        uint4 a4[5], b4[5], t4[5];
        #pragma unroll
        for (int g = 0; g < 5; g++) { a4[g] = Ar[g]; b4[g] = Br[g]; t4[g] = Tr[g]; }
        #pragma unroll
        for (int g = 0; g < 5; g++) {
            int cc0 = qq * 40 + g * 8;
            uint32_t addr = Hb + (uint32_t)((cc0 >> 6) * 16384) +
                            SWZ((uint32_t)(r * 128 + (cc0 & 63) * 2));
            uint32_t h0, h1, h2, h3;
            LDS128(h0, h1, h2, h3, addr);
            uint32_t hw[4] = {h0, h1, h2, h3};
            const uint32_t* ap = (const uint32_t*)&a4[g];
            const uint32_t* bp = (const uint32_t*)&b4[g];
            const uint32_t* tp = (const uint32_t*)&t4[g];
            #pragma unroll
            for (int wv = 0; wv < 4; wv++) {
                float2 hv = unpack_bf2(hw[wv]);
                float2 av = unpack_bf2(ap[wv]);
                float2 bv = unpack_bf2(bp[wv]);
                float2 tv = unpack_bf2(tp[wv]);
                float x = fmaxf(hv.x + av.x + bv.x + tv.x, 0.f);
                float y = fmaxf(hv.y + av.y + bv.y + tv.y, 0.f);
                CVTB2(hw[wv], x, y);
            }
            STS128(hw[0], hw[1], hw[2], hw[3], addr);
        }
    }
    CPW0();
    __syncthreads();

    // ---- layer 2 ----
    #pragma unroll
    for (int i = 0; i < 2; i++)
        #pragma unroll
        for (int j = 0; j < 5; j++)
            #pragma unroll
            for (int k = 0; k < 4; k++) acc[i][j][k] = 0.f;
    #pragma unroll
    for (int ch = 0; ch < 3; ch++) {
        int nk = (ch == 2) ? 2 : 4;
        if (nw < 3) mma_chunk40<2,true >(Hb + ch * 16384, W2b + ch * CHB, nk, mw * 32, nw * 40, lane, acc);
        else        mma_chunk40<2,false>(Hb + ch * 16384, W2b + ch * CHB, nk, mw * 32, nw * 40, lane, acc);
    }

    // ---- epilogue 2: relu(+b2) . W3 -> reduce -> scores ----
    #pragma unroll
    for (int mt = 0; mt < 2; mt++)
        #pragma unroll
        for (int half = 0; half < 2; half++) {
            float part = 0.f;
            #pragma unroll
            for (int nt = 0; nt < 5; nt++) {
                int cc = nw * 40 + nt * 8 + (lane & 3) * 2;
                float h0 = fmaxf(acc[mt][nt][half * 2]     + s_b2[cc],     0.f);
                float h1 = fmaxf(acc[mt][nt][half * 2 + 1] + s_b2[cc + 1], 0.f);
                part += h0 * s_w3[cc] + h1 * s_w3[cc + 1];
            }
            part += __shfl_xor_sync(0xffffffffu, part, 1);
            part += __shfl_xor_sync(0xffffffffu, part, 2);
            if ((lane & 3) == 0) {
                int r = mw * 32 + mt * 16 + (lane >> 2) + half * 8;
                sred[r][nw] = part;
            }
        }
    __syncthreads();
    if (tid < 128) {
        int p = p0 + tid;
        if (p < P) {
            float s = sred[tid][0] + sred[tid][1] + sred[tid][2] + sred[tid][3]
                    + b3[0] + ms[smi[tid]] + ms[sai[tid]];
            g_scores[p] = s;
        }
    }
}

// ============================================================
// softmax: 4 groups per 512-thread block
// ============================================================
__global__ __launch_bounds__(512) void k_softmax(const int* __restrict__ lengths,
                                                 float* __restrict__ out, int M)
{
    __shared__ float sm[4][4], ss[4][4];
    int gg = threadIdx.x >> 7;          // group slot 0..3
    int tid = threadIdx.x & 127;
    int g = blockIdx.x * 4 + gg;
    bool ok = (g < M);
    int len = ok ? lengths[g] : 0;
    int st  = ok ? g_starts[g] : 0;

    float v = (ok && tid < len) ? g_scores[st + tid] : -3.4e38f;
    float mx = v;
    #pragma unroll
    for (int o = 16; o > 0; o >>= 1) mx = fmaxf(mx, __shfl_xor_sync(0xffffffffu, mx, o));
    if ((tid & 31) == 0) sm[gg][tid >> 5] = mx;
    __syncthreads();
    mx = fmaxf(fmaxf(sm[gg][0], sm[gg][1]), fmaxf(sm[gg][2], sm[gg][3]));
    mx = fmaxf(mx, 0.f);

    float e = (ok && tid < len) ? expf(v - mx) : 0.f;
    float s = e;
    #pragma unroll
    for (int o = 16; o > 0; o >>= 1) s += __shfl_xor_sync(0xffffffffu, s, o);
    if ((tid & 31) == 0) ss[gg][tid >> 5] = s;
    __syncthreads();

    if (ok) {
        float epse = expf(-mx);
        float denom = ss[gg][0] + ss[gg][1] + ss[gg][2] + ss[gg][3] + epse;
        float* row = out + (size_t)(g + 1) * GRIDW;
        if (tid < len) row[tid] = e / denom;
        if (tid == 0)  row[len] = epse / denom;
    }
}

// ============================================================
extern "C" void kernel_launch(void* const* d_in, const int* in_sizes, int n_in,
                              void* d_out, int out_size)
{
    const float* gi   = (const float*)d_in[0];
    const float* ms   = (const float*)d_in[1];
    const float* de   = (const float*)d_in[2];
    const float* ge   = (const float*)d_in[3];
    const float* se   = (const float*)d_in[4];
    const float* W1   = (const float*)d_in[5];
    const float* b1   = (const float*)d_in[6];
    const float* W2   = (const float*)d_in[7];
    const float* b2   = (const float*)d_in[8];
    const float* W3   = (const float*)d_in[9];
    const float* b3   = (const float*)d_in[10];
    const int*   mi   = (const int*)d_in[11];
    const int*   ai   = (const int*)d_in[12];
    const int*   di   = (const int*)d_in[13];
    const int*   gidx = (const int*)d_in[14];
    const int*   si   = (const int*)d_in[15];
    const int*   lens = (const int*)d_in[16];
    const int*   segs = (const int*)d_in[17];
    const int*   offs = (const int*)d_in[18];
    float* out = (float*)d_out;

    const int P = in_sizes[11];
    const int M = in_sizes[16];
    const int NSPAN = in_sizes[0] / GDIM;   // 4096

    const int DS_PRE   = 73728 + 1024;
    const int DS_FUSED = 110592 + 1024;
    static int configured = 0;
    if (!configured) {
        cudaFuncSetAttribute(k_pre,   cudaFuncAttributeMaxDynamicSharedMemorySize, DS_PRE);
        cudaFuncSetAttribute(k_fused, cudaFuncAttributeMaxDynamicSharedMemorySize, DS_FUSED);
        configured = 1;
    }

    long long prep_total = (long long)NSPAN * 128 + (2 * 16 + NCHUNK + 3) * CHW
                         + 216 * 80 + out_size + P;
    k_prep<<<(int)((prep_total + 255) / 256), 256>>>(gi, W1, W2, de, ge, se,
                                                     offs, segs, out,
                                                     NSPAN, P, out_size);

    k_pre<<<dim3(NSPAN / 64, 2, 2), 256, DS_PRE>>>(b1);

    int NT = (P + 127) / 128;
    k_fused<<<NT, 512, DS_FUSED>>>(b2, W3, b3, ms,
                                   mi, ai, di, gidx, si, P);

    k_softmax<<<(M + 3) / 4, 512>>>(lens, out, M);
}